// round 14
// baseline (speedup 1.0000x reference)
#include <cuda_runtime.h>
#include <cuda_fp16.h>
#include <math.h>
#include <cstdint>

// Problem constants
#define BB 4
#define SS 2048
#define DD 2048
#define HH 16
#define HD 128
#define F3D (3*DD)          // 6144
#define MROWS (BB*SS)       // 8192

// Scratch (device globals; no allocation allowed)
__device__ __half g_xh[(size_t)MROWS * DD];
__device__ __half g_win_h[(size_t)F3D * DD];
__device__ __half g_wout_h[(size_t)DD * DD];
__device__ float  g_qkv[(size_t)MROWS * F3D];
__device__ __half g_qh[(size_t)MROWS * DD];
__device__ __half g_ql[(size_t)MROWS * DD];
__device__ __half g_kh[(size_t)MROWS * DD];
__device__ __half g_kl[(size_t)MROWS * DD];
__device__ unsigned g_vt[(size_t)BB * HH * HD * (SS/2)];
__device__ __half g_ah[(size_t)MROWS * DD];

extern __shared__ __align__(16) char dyn_smem[];

// ---------------------------------------------------------------------------
__device__ __forceinline__ uint32_t smem_to_u32(const void* p) {
    uint32_t a;
    asm("{ .reg .u64 t; cvta.to.shared.u64 t, %1; cvt.u32.u64 %0, t; }" : "=r"(a) : "l"(p));
    return a;
}
__device__ __forceinline__ void cp_async16(uint32_t saddr, const void* gptr) {
    asm volatile("cp.async.cg.shared.global [%0], [%1], 16;" :: "r"(saddr), "l"(gptr));
}
#define CP_COMMIT() asm volatile("cp.async.commit_group;" ::: "memory")
#define CP_WAIT1()  asm volatile("cp.async.wait_group 1;" ::: "memory")
#define CP_WAIT0()  asm volatile("cp.async.wait_group 0;" ::: "memory")

__device__ __forceinline__ void mma_f16(float* c, const unsigned* a, const unsigned* b) {
    asm volatile(
        "mma.sync.aligned.m16n8k16.row.col.f32.f16.f16.f32 "
        "{%0,%1,%2,%3}, {%4,%5,%6,%7}, {%8,%9}, {%0,%1,%2,%3};"
        : "+f"(c[0]), "+f"(c[1]), "+f"(c[2]), "+f"(c[3])
        : "r"(a[0]), "r"(a[1]), "r"(a[2]), "r"(a[3]), "r"(b[0]), "r"(b[1]));
}
__device__ __forceinline__ void ldsm_x4(unsigned& r0, unsigned& r1, unsigned& r2,
                                        unsigned& r3, uint32_t addr) {
    asm volatile("ldmatrix.sync.aligned.m8n8.x4.shared.b16 {%0,%1,%2,%3}, [%4];"
        : "=r"(r0), "=r"(r1), "=r"(r2), "=r"(r3) : "r"(addr));
}
__device__ __forceinline__ unsigned pack_h2(float lo, float hi) {
    __half2 h = __floats2half2_rn(lo, hi);
    return *(unsigned*)&h;
}

// ---------------------------------------------------------------------------
__global__ void __launch_bounds__(256) cvt_f2h(const float* __restrict__ x,
                                               __half* __restrict__ xh)
{
    size_t i = ((size_t)blockIdx.x * 256 + threadIdx.x) * 4;
    float4 v = *(const float4*)(x + i);
    unsigned* o = (unsigned*)(xh + i);
    o[0] = pack_h2(v.x, v.y);
    o[1] = pack_h2(v.z, v.w);
}

// ---------------------------------------------------------------------------
__global__ void __launch_bounds__(256) unit_norm_rows_h(
    const float* __restrict__ w, __half* __restrict__ o, int cols)
{
    int row = blockIdx.x, tid = threadIdx.x;
    const float* src = w + (size_t)row * cols;
    __half* dst = o + (size_t)row * cols;
    float ss = 0.f;
    for (int i = tid * 4; i < cols; i += 1024) {
        float4 v = *(const float4*)(src + i);
        ss += v.x*v.x + v.y*v.y + v.z*v.z + v.w*v.w;
    }
    #pragma unroll
    for (int off = 16; off; off >>= 1) ss += __shfl_xor_sync(0xffffffffu, ss, off);
    __shared__ float red[8];
    if ((tid & 31) == 0) red[tid >> 5] = ss;
    __syncthreads();
    float total = 0.f;
    #pragma unroll
    for (int i = 0; i < 8; i++) total += red[i];
    float r = rsqrtf(total + 1e-6f);
    for (int i = tid * 4; i < cols; i += 1024) {
        float4 v = *(const float4*)(src + i);
        unsigned* op = (unsigned*)(dst + i);
        op[0] = pack_h2(v.x * r, v.y * r);
        op[1] = pack_h2(v.z * r, v.w * r);
    }
}

// ---------------------------------------------------------------------------
// FP16 GEMM: 256x128 CTA tile, BK=32, 3-stage cp.async ring, ldmatrix.
// 512 threads / 16 warps (4x4 grid of 64x32 warp tiles).
// smem per stage: A 256x40 + B 128x40 halfwords = 30720 B; 3 stages = 92160 B.
// ---------------------------------------------------------------------------
#define HBKP 40
#define HSTG_B 30720
#define GEMM_SMEM (3 * HSTG_B)

__global__ void __launch_bounds__(512, 1) gemm_fp16(
    const __half* __restrict__ A, const __half* __restrict__ B,
    float* __restrict__ C, int M, int N, int K)
{
    int tid = threadIdx.x, lane = tid & 31, warp = tid >> 5;
    int wm = warp >> 2, wn = warp & 3;          // 4x4 warp grid
    int mBase = blockIdx.y * 256, nBase = blockIdx.x * 128;
    int lr = lane >> 2, lc = lane & 3;
    int l7 = lane & 7, l8 = (lane >> 3) & 1, l16 = lane >> 4;

    // staging: A 1024 chunks (rows 0..255 x 4), B 512 chunks (rows 0..127 x 4)
    int rA = tid >> 2, chA = (tid & 3) * 8;     // A rows 0..127 (+128 for 2nd)
    const __half* Ap0 = A + (size_t)(mBase + rA) * K + chA;
    const __half* Ap1 = A + (size_t)(mBase + rA + 128) * K + chA;
    const __half* Bp  = B + (size_t)(nBase + rA) * K + chA;   // rA<128 only for B

    uint32_t sb = smem_to_u32(dyn_smem);
    uint32_t sA0 = sb + (rA * HBKP + chA) * 2;
    uint32_t sA1 = sA0 + 128 * HBKP * 2;
    uint32_t sB  = sb + (256 * HBKP + rA * HBKP + chA) * 2;   // B base after A
    bool doB = (rA < 128);
    // threads with rA>=128 handle B rows 0..127 via rA-128? No: rA in 0..127 always
    // (tid>>2 max = 511>>2 = 127). All threads do A0, A1, B. rA in [0,127]. OK.

    uint32_t aOff[4], bOff[2];
    #pragma unroll
    for (int mf = 0; mf < 4; mf++)
        aOff[mf] = ((wm * 64 + mf * 16 + l7 + l8 * 8) * HBKP + l16 * 8) * 2;
    #pragma unroll
    for (int nfp = 0; nfp < 2; nfp++)
        bOff[nfp] = (256 * HBKP + (wn * 32 + nfp * 16 + l16 * 8 + l7) * HBKP + l8 * 8) * 2;

    float acc[4][4][4];
    #pragma unroll
    for (int i = 0; i < 4; i++)
        #pragma unroll
        for (int j = 0; j < 4; j++)
            #pragma unroll
            for (int l = 0; l < 4; l++) acc[i][j][l] = 0.f;

    const int T = K / 32;

    #pragma unroll
    for (int s = 0; s < 2; s++) {
        uint32_t so = s * HSTG_B;
        int k0 = s * 32;
        cp_async16(sA0 + so, Ap0 + k0);
        cp_async16(sA1 + so, Ap1 + k0);
        cp_async16(sB + so,  Bp + k0);
        CP_COMMIT();
    }

    for (int t = 0; t < T; t++) {
        CP_WAIT1();
        __syncthreads();

        if (t + 2 < T) {
            uint32_t so = ((t + 2) % 3) * HSTG_B;
            int k0 = (t + 2) * 32;
            cp_async16(sA0 + so, Ap0 + k0);
            cp_async16(sA1 + so, Ap1 + k0);
            cp_async16(sB + so,  Bp + k0);
        }
        CP_COMMIT();

        uint32_t sS = sb + (t % 3) * HSTG_B;
        #pragma unroll
        for (int ch = 0; ch < 2; ch++) {
            uint32_t cB = ch * 32;
            unsigned a[4][4], b[4][2];
            #pragma unroll
            for (int mf = 0; mf < 4; mf++)
                ldsm_x4(a[mf][0], a[mf][1], a[mf][2], a[mf][3], sS + aOff[mf] + cB);
            #pragma unroll
            for (int nfp = 0; nfp < 2; nfp++) {
                unsigned q0, q1, q2, q3;
                ldsm_x4(q0, q1, q2, q3, sS + bOff[nfp] + cB);
                b[2*nfp][0] = q0; b[2*nfp][1] = q1;
                b[2*nfp+1][0] = q2; b[2*nfp+1][1] = q3;
            }
            #pragma unroll
            for (int mf = 0; mf < 4; mf++)
                #pragma unroll
                for (int nf = 0; nf < 4; nf++)
                    mma_f16(acc[mf][nf], a[mf], b[nf]);
        }
    }

    #pragma unroll
    for (int mf = 0; mf < 4; mf++) {
        int row = mBase + wm * 64 + mf * 16 + lr;
        #pragma unroll
        for (int nf = 0; nf < 4; nf++) {
            int col = nBase + wn * 32 + nf * 8 + lc * 2;
            float2 v0 = {acc[mf][nf][0], acc[mf][nf][1]};
            float2 v1 = {acc[mf][nf][2], acc[mf][nf][3]};
            *(float2*)(C + (size_t)row * N + col)       = v0;
            *(float2*)(C + (size_t)(row + 8) * N + col) = v1;
        }
    }
    (void)doB;
}

// ---------------------------------------------------------------------------
// prep_qk: rms_norm q,k rows + split into (hi,lo) fp16 globals. 1 warp/row.
// ---------------------------------------------------------------------------
__global__ void __launch_bounds__(256) prep_qk(
    const float* __restrict__ qkv,
    __half* __restrict__ qh, __half* __restrict__ ql,
    __half* __restrict__ kh, __half* __restrict__ kl)
{
    int gw = (blockIdx.x * blockDim.x + threadIdx.x) >> 5;
    int lane = threadIdx.x & 31;
    int which = gw & 1;
    int t = gw >> 1;
    int h = t % HH;
    int bs = t / HH;
    const float* p = qkv + (size_t)bs * F3D + which * DD + h * HD + lane * 4;
    float4 v = *(const float4*)p;
    float ss = v.x*v.x + v.y*v.y + v.z*v.z + v.w*v.w;
    #pragma unroll
    for (int off = 16; off; off >>= 1) ss += __shfl_xor_sync(0xffffffffu, ss, off);
    float r = rsqrtf(ss * (1.f / HD) + 1e-6f);
    v.x *= r; v.y *= r; v.z *= r; v.w *= r;

    size_t oidx = (size_t)bs * DD + h * HD + lane * 4;
    __half* oh = (which ? kh : qh) + oidx;
    __half* ol = (which ? kl : ql) + oidx;
    unsigned hxy = pack_h2(v.x, v.y), hzw = pack_h2(v.z, v.w);
    __half2 hh0 = *(__half2*)&hxy, hh1 = *(__half2*)&hzw;
    float2 f0 = __half22float2(hh0), f1 = __half22float2(hh1);
    uint2 hi = {hxy, hzw};
    uint2 lo = {pack_h2(v.x - f0.x, v.y - f0.y), pack_h2(v.z - f1.x, v.w - f1.y)};
    *(uint2*)oh = hi;
    *(uint2*)ol = lo;
}

// ---------------------------------------------------------------------------
// vprep: pack V into transposed key-pair half2 layout [b,h,d,key2].
// ---------------------------------------------------------------------------
__global__ void __launch_bounds__(256) vprep(
    const float* __restrict__ qkv, unsigned* __restrict__ vt)
{
    int id = blockIdx.x * 256 + threadIdx.x;
    int lane = id & 31;
    int idx = id >> 5;
    int d4 = idx & 31;
    int k2b = (idx >> 5) & 31;
    int bh = idx >> 10;
    int b = bh >> 4, h = bh & 15;
    int key2 = k2b * 32 + lane;

    const float* p0 = qkv + ((size_t)(b * SS + 2 * key2)) * F3D + 2 * DD + h * HD + d4 * 4;
    float4 va = *(const float4*)p0;
    float4 vb = *(const float4*)(p0 + F3D);
    size_t base = ((size_t)bh * HD + d4 * 4) * (SS / 2) + key2;
    vt[base]                = pack_h2(va.x, vb.x);
    vt[base + (SS/2)]       = pack_h2(va.y, vb.y);
    vt[base + 2*(SS/2)]     = pack_h2(va.z, vb.z);
    vt[base + 3*(SS/2)]     = pack_h2(va.w, vb.w);
}

// ---------------------------------------------------------------------------
// FP16 flash attention (round-13 version, unchanged).
// ---------------------------------------------------------------------------
#define QST 68
#define KST 68
#define VST2 36
#define PST 36
#define KVU (64*KST*2 + 128*VST2)
#define ATT_SMEM ((128*QST*2 + 2*KVU + 128*PST) * 4)

__global__ void __launch_bounds__(256) flash_attn_fp16(
    const __half* __restrict__ qh, const __half* __restrict__ ql,
    const __half* __restrict__ kh, const __half* __restrict__ kl,
    const unsigned* __restrict__ vt, __half* __restrict__ out)
{
    uint32_t sbase = smem_to_u32(dyn_smem);
    uint32_t uQh = sbase;
    uint32_t uQl = sbase + 8704u * 4;
    uint32_t uKV0 = sbase + 17408u * 4;
    uint32_t uPp = sbase + (17408u + 2 * KVU) * 4;
    unsigned* Pp = (unsigned*)dyn_smem + 17408 + 2 * KVU;

    int tid = threadIdx.x, lane = tid & 31, wid = tid >> 5;
    int lr = lane >> 2, lc = lane & 3;
    int l7 = lane & 7, l8 = (lane >> 3) & 1, l16 = lane >> 4;
    int b = blockIdx.z, h = blockIdx.y;
    int qb = (int)gridDim.x - 1 - (int)blockIdx.x;
    int wrow = wid * 16;
    int bh = b * HH + h;

    uint32_t qOff = ((wrow + l7 + l8 * 8) * QST + l16 * 4) * 4;
    uint32_t pOff = ((wrow + l7 + l8 * 8) * PST + l16 * 4) * 4;
    uint32_t kOff[4], vOff[8];
    #pragma unroll
    for (int nfp = 0; nfp < 4; nfp++)
        kOff[nfp] = ((nfp * 16 + l16 * 8 + l7) * KST + l8 * 4) * 4;
    #pragma unroll
    for (int nfp = 0; nfp < 8; nfp++)
        vOff[nfp] = (8704u + (nfp * 16 + l16 * 8 + l7) * VST2 + l8 * 4) * 4;

    const float scale = 0.08838834764831845f;

    {
        const __half* qhb = qh + ((size_t)(b * SS + qb * 128)) * DD + h * HD;
        const __half* qlb = ql + ((size_t)(b * SS + qb * 128)) * DD + h * HD;
        #pragma unroll
        for (int j = 0; j < 8; j++) {
            int lin = j * 256 + tid;
            int row = lin >> 4, ch = lin & 15;
            uint32_t d = (row * QST + ch * 4) * 4;
            cp_async16(uQh + d, qhb + (size_t)row * DD + ch * 8);
            cp_async16(uQl + d, qlb + (size_t)row * DD + ch * 8);
        }
    }

    int nIter = 2 * (qb + 1);
    const __half* khb = kh + (size_t)(b * SS) * DD + h * HD;
    const __half* klb = kl + (size_t)(b * SS) * DD + h * HD;
    const unsigned* vtb = vt + (size_t)bh * HD * (SS / 2);

    {
        #pragma unroll
        for (int j = 0; j < 4; j++) {
            int lin = j * 256 + tid;
            int row = lin >> 4, ch = lin & 15;
            uint32_t d = uKV0 + (row * KST + ch * 4) * 4;
            cp_async16(d, khb + (size_t)row * DD + ch * 8);
            cp_async16(d + 4352u * 4, klb + (size_t)row * DD + ch * 8);
        }
        #pragma unroll
        for (int j = 0; j < 4; j++) {
            int lin = j * 256 + tid;
            int dd = lin >> 3, ch = lin & 7;
            cp_async16(uKV0 + (8704u + dd * VST2 + ch * 4) * 4,
                       vtb + (size_t)dd * (SS / 2) + ch * 4);
        }
        CP_COMMIT();
    }

    float o[16][4];
    #pragma unroll
    for (int i = 0; i < 16; i++)
        #pragma unroll
        for (int j = 0; j < 4; j++) o[i][j] = 0.f;
    float m0 = -INFINITY, m1 = -INFINITY, l0 = 0.f, l1 = 0.f;

    int gr0 = qb * 128 + wrow + lr;
    int wmin = qb * 128 + wrow;

    for (int t = 0; t < nIter; t++) {
        int k0 = t * 64;
        uint32_t uS = uKV0 + (uint32_t)(t & 1) * (KVU * 4);

        if (t + 1 < nIter) {
            uint32_t uN = uKV0 + (uint32_t)((t + 1) & 1) * (KVU * 4);
            int kn = (t + 1) * 64;
            #pragma unroll
            for (int j = 0; j < 4; j++) {
                int lin = j * 256 + tid;
                int row = lin >> 4, ch = lin & 15;
                uint32_t d = uN + (row * KST + ch * 4) * 4;
                cp_async16(d, khb + (size_t)(kn + row) * DD + ch * 8);
                cp_async16(d + 4352u * 4, klb + (size_t)(kn + row) * DD + ch * 8);
            }
            #pragma unroll
            for (int j = 0; j < 4; j++) {
                int lin = j * 256 + tid;
                int dd = lin >> 3, ch = lin & 7;
                cp_async16(uN + (8704u + dd * VST2 + ch * 4) * 4,
                           vtb + (size_t)dd * (SS / 2) + kn / 2 + ch * 4);
            }
            CP_COMMIT();
            CP_WAIT1();
        } else {
            CP_WAIT0();
        }
        __syncthreads();

        // ---- S = Q K^T : 3-term fp16 ----
        float s[8][4];
        #pragma unroll
        for (int nf = 0; nf < 8; nf++)
            #pragma unroll
            for (int j = 0; j < 4; j++) s[nf][j] = 0.f;

        #pragma unroll
        for (int ks = 0; ks < 8; ks++) {
            unsigned ah[4], al[4];
            ldsm_x4(ah[0], ah[1], ah[2], ah[3], uQh + qOff + ks * 32);
            ldsm_x4(al[0], al[1], al[2], al[3], uQl + qOff + ks * 32);
            #pragma unroll
            for (int nfp = 0; nfp < 4; nfp++) {
                unsigned h0, h1, h2, h3, g0, g1, g2, g3;
                ldsm_x4(h0, h1, h2, h3, uS + kOff[nfp] + ks * 32);
                ldsm_x4(g0, g1, g2, g3, uS + 4352u * 4 + kOff[nfp] + ks * 32);
                unsigned bh0[2] = {h0, h1}, bh1[2] = {h2, h3};
                unsigned bl0[2] = {g0, g1}, bl1[2] = {g2, g3};
                mma_f16(s[2*nfp],   ah, bh0);
                mma_f16(s[2*nfp],   ah, bl0);
                mma_f16(s[2*nfp],   al, bh0);
                mma_f16(s[2*nfp+1], ah, bh1);
                mma_f16(s[2*nfp+1], ah, bl1);
                mma_f16(s[2*nfp+1], al, bh1);
            }
        }

        // ---- scale (+ causal mask only on diagonal-crossing tiles) ----
        if (k0 + 63 >= wmin) {
            #pragma unroll
            for (int nf = 0; nf < 8; nf++) {
                int c0 = k0 + nf * 8 + lc * 2;
                s[nf][0] = (c0     > gr0)     ? -INFINITY : s[nf][0] * scale;
                s[nf][1] = (c0 + 1 > gr0)     ? -INFINITY : s[nf][1] * scale;
                s[nf][2] = (c0     > gr0 + 8) ? -INFINITY : s[nf][2] * scale;
                s[nf][3] = (c0 + 1 > gr0 + 8) ? -INFINITY : s[nf][3] * scale;
            }
        } else {
            #pragma unroll
            for (int nf = 0; nf < 8; nf++) {
                s[nf][0] *= scale; s[nf][1] *= scale;
                s[nf][2] *= scale; s[nf][3] *= scale;
            }
        }

        // ---- online softmax ----
        float mn0 = m0, mn1 = m1;
        #pragma unroll
        for (int nf = 0; nf < 8; nf++) {
            mn0 = fmaxf(mn0, fmaxf(s[nf][0], s[nf][1]));
            mn1 = fmaxf(mn1, fmaxf(s[nf][2], s[nf][3]));
        }
        mn0 = fmaxf(mn0, __shfl_xor_sync(0xffffffffu, mn0, 1));
        mn0 = fmaxf(mn0, __shfl_xor_sync(0xffffffffu, mn0, 2));
        mn1 = fmaxf(mn1, __shfl_xor_sync(0xffffffffu, mn1, 1));
        mn1 = fmaxf(mn1, __shfl_xor_sync(0xffffffffu, mn1, 2));

        float corr0 = __expf(m0 - mn0), corr1 = __expf(m1 - mn1);
        m0 = mn0; m1 = mn1;

        float ps0 = 0.f, ps1 = 0.f;
        int r = wrow + lr;
        #pragma unroll
        for (int nf = 0; nf < 8; nf++) {
            float p0 = __expf(s[nf][0] - mn0);
            float p1 = __expf(s[nf][1] - mn0);
            float p2 = __expf(s[nf][2] - mn1);
            float p3 = __expf(s[nf][3] - mn1);
            ps0 += p0 + p1; ps1 += p2 + p3;
            int key2 = nf * 4 + lc;
            Pp[r * PST + key2]       = pack_h2(p0, p1);
            Pp[(r + 8) * PST + key2] = pack_h2(p2, p3);
        }
        ps0 += __shfl_xor_sync(0xffffffffu, ps0, 1);
        ps0 += __shfl_xor_sync(0xffffffffu, ps0, 2);
        ps1 += __shfl_xor_sync(0xffffffffu, ps1, 1);
        ps1 += __shfl_xor_sync(0xffffffffu, ps1, 2);
        l0 = l0 * corr0 + ps0;
        l1 = l1 * corr1 + ps1;

        #pragma unroll
        for (int nf = 0; nf < 16; nf++) {
            o[nf][0] *= corr0; o[nf][1] *= corr0;
            o[nf][2] *= corr1; o[nf][3] *= corr1;
        }
        __syncwarp();

        // ---- O += P V ----
        #pragma unroll
        for (int ks = 0; ks < 4; ks++) {
            unsigned a4[4];
            ldsm_x4(a4[0], a4[1], a4[2], a4[3], uPp + pOff + ks * 32);
            #pragma unroll
            for (int nfp = 0; nfp < 8; nfp++) {
                unsigned q0, q1, q2, q3;
                ldsm_x4(q0, q1, q2, q3, uS + vOff[nfp] + ks * 32);
                unsigned b0[2] = {q0, q1}, b1[2] = {q2, q3};
                mma_f16(o[2*nfp],   a4, b0);
                mma_f16(o[2*nfp+1], a4, b1);
            }
        }
        __syncthreads();
    }

    // ---- epilogue ----
    float il0 = 1.f / l0, il1 = 1.f / l1;
    float ss0 = 0.f, ss1 = 0.f;
    #pragma unroll
    for (int nf = 0; nf < 16; nf++) {
        o[nf][0] *= il0; o[nf][1] *= il0;
        o[nf][2] *= il1; o[nf][3] *= il1;
        ss0 += o[nf][0]*o[nf][0] + o[nf][1]*o[nf][1];
        ss1 += o[nf][2]*o[nf][2] + o[nf][3]*o[nf][3];
    }
    ss0 += __shfl_xor_sync(0xffffffffu, ss0, 1);
    ss0 += __shfl_xor_sync(0xffffffffu, ss0, 2);
    ss1 += __shfl_xor_sync(0xffffffffu, ss1, 1);
    ss1 += __shfl_xor_sync(0xffffffffu, ss1, 2);
    float rn0 = rsqrtf(ss0 * (1.f / HD) + 1e-6f);
    float rn1 = rsqrtf(ss1 * (1.f / HD) + 1e-6f);

    __half* o0 = out + ((size_t)(b * SS + gr0)) * DD + h * HD;
    __half* o1 = out + ((size_t)(b * SS + gr0 + 8)) * DD + h * HD;
    #pragma unroll
    for (int nf = 0; nf < 16; nf++) {
        int col = nf * 8 + lc * 2;
        *(unsigned*)(o0 + col) = pack_h2(o[nf][0] * rn0, o[nf][1] * rn0);
        *(unsigned*)(o1 + col) = pack_h2(o[nf][2] * rn1, o[nf][3] * rn1);
    }
}

// ---------------------------------------------------------------------------
extern "C" void kernel_launch(void* const* d_in, const int* in_sizes, int n_in,
                              void* d_out, int out_size)
{
    const float* x = nullptr; const float* w_in = nullptr; const float* w_out = nullptr;
    for (int i = 0; i < n_in; i++) {
        if (in_sizes[i] == BB * SS * DD)      x     = (const float*)d_in[i];
        else if (in_sizes[i] == F3D * DD)     w_in  = (const float*)d_in[i];
        else if (in_sizes[i] == DD * DD)      w_out = (const float*)d_in[i];
    }

    __half* xh;     cudaGetSymbolAddress((void**)&xh, g_xh);
    __half* win_h;  cudaGetSymbolAddress((void**)&win_h, g_win_h);
    __half* wout_h; cudaGetSymbolAddress((void**)&wout_h, g_wout_h);
    float*  qkv;    cudaGetSymbolAddress((void**)&qkv, g_qkv);
    __half* qh;     cudaGetSymbolAddress((void**)&qh, g_qh);
    __half* ql;     cudaGetSymbolAddress((void**)&ql, g_ql);
    __half* kh;     cudaGetSymbolAddress((void**)&kh, g_kh);
    __half* kl;     cudaGetSymbolAddress((void**)&kl, g_kl);
    unsigned* vt;   cudaGetSymbolAddress((void**)&vt, g_vt);
    __half* ah;     cudaGetSymbolAddress((void**)&ah, g_ah);

    cudaFuncSetAttribute(gemm_fp16, cudaFuncAttributeMaxDynamicSharedMemorySize, GEMM_SMEM);
    cudaFuncSetAttribute(flash_attn_fp16, cudaFuncAttributeMaxDynamicSharedMemorySize, ATT_SMEM);

    cvt_f2h<<<(MROWS * DD) / 1024, 256>>>(x, xh);
    unit_norm_rows_h<<<F3D, 256>>>(w_in, win_h, DD);
    unit_norm_rows_h<<<DD, 256>>>(w_out, wout_h, DD);

    {
        dim3 grid(F3D / 128, MROWS / 256);
        gemm_fp16<<<grid, 512, GEMM_SMEM>>>(xh, win_h, qkv, MROWS, F3D, DD);
    }
    {
        int blocks = (MROWS * 2 * HH) * 32 / 256;
        prep_qk<<<blocks, 256>>>(qkv, qh, ql, kh, kl);
        vprep<<<(BB * HH * 32 * 32 * 32) / 256, 256>>>(qkv, vt);
    }
    {
        dim3 grid(SS / 128, HH, BB);
        flash_attn_fp16<<<grid, 256, ATT_SMEM>>>(qh, ql, kh, kl, vt, ah);
    }
    {
        dim3 grid(DD / 128, MROWS / 256);
        gemm_fp16<<<grid, 512, GEMM_SMEM>>>(ah, wout_h, (float*)d_out, MROWS, DD, DD);
    }
}

// round 15
// speedup vs baseline: 1.1539x; 1.1539x over previous
#include <cuda_runtime.h>
#include <cuda_fp16.h>
#include <math.h>
#include <cstdint>

// Problem constants
#define BB 4
#define SS 2048
#define DD 2048
#define HH 16
#define HD 128
#define F3D (3*DD)          // 6144
#define MROWS (BB*SS)       // 8192

// Scratch (device globals; no allocation allowed)
__device__ __half g_xh[(size_t)MROWS * DD];
__device__ __half g_win_h[(size_t)F3D * DD];
__device__ __half g_wout_h[(size_t)DD * DD];
__device__ float  g_qkv[(size_t)MROWS * F3D];
__device__ __half g_qh[(size_t)MROWS * DD];
__device__ __half g_ql[(size_t)MROWS * DD];
__device__ __half g_kh[(size_t)MROWS * DD];
__device__ __half g_kl[(size_t)MROWS * DD];
__device__ unsigned g_vt[(size_t)BB * HH * HD * (SS/2)];
__device__ __half g_ah[(size_t)MROWS * DD];

extern __shared__ __align__(16) char dyn_smem[];

// ---------------------------------------------------------------------------
__device__ __forceinline__ uint32_t smem_to_u32(const void* p) {
    uint32_t a;
    asm("{ .reg .u64 t; cvta.to.shared.u64 t, %1; cvt.u32.u64 %0, t; }" : "=r"(a) : "l"(p));
    return a;
}
__device__ __forceinline__ void cp_async16(uint32_t saddr, const void* gptr) {
    asm volatile("cp.async.cg.shared.global [%0], [%1], 16;" :: "r"(saddr), "l"(gptr));
}
#define CP_COMMIT() asm volatile("cp.async.commit_group;" ::: "memory")
#define CP_WAIT1()  asm volatile("cp.async.wait_group 1;" ::: "memory")
#define CP_WAIT0()  asm volatile("cp.async.wait_group 0;" ::: "memory")

__device__ __forceinline__ void mma_f16(float* c, const unsigned* a, const unsigned* b) {
    asm volatile(
        "mma.sync.aligned.m16n8k16.row.col.f32.f16.f16.f32 "
        "{%0,%1,%2,%3}, {%4,%5,%6,%7}, {%8,%9}, {%0,%1,%2,%3};"
        : "+f"(c[0]), "+f"(c[1]), "+f"(c[2]), "+f"(c[3])
        : "r"(a[0]), "r"(a[1]), "r"(a[2]), "r"(a[3]), "r"(b[0]), "r"(b[1]));
}
__device__ __forceinline__ void ldsm_x4(unsigned& r0, unsigned& r1, unsigned& r2,
                                        unsigned& r3, uint32_t addr) {
    asm volatile("ldmatrix.sync.aligned.m8n8.x4.shared.b16 {%0,%1,%2,%3}, [%4];"
        : "=r"(r0), "=r"(r1), "=r"(r2), "=r"(r3) : "r"(addr));
}
__device__ __forceinline__ unsigned pack_h2(float lo, float hi) {
    __half2 h = __floats2half2_rn(lo, hi);
    return *(unsigned*)&h;
}

// ---------------------------------------------------------------------------
__global__ void __launch_bounds__(256) cvt_f2h(const float* __restrict__ x,
                                               __half* __restrict__ xh)
{
    size_t i = ((size_t)blockIdx.x * 256 + threadIdx.x) * 4;
    float4 v = *(const float4*)(x + i);
    unsigned* o = (unsigned*)(xh + i);
    o[0] = pack_h2(v.x, v.y);
    o[1] = pack_h2(v.z, v.w);
}

// ---------------------------------------------------------------------------
__global__ void __launch_bounds__(256) unit_norm_rows_h(
    const float* __restrict__ w, __half* __restrict__ o, int cols)
{
    int row = blockIdx.x, tid = threadIdx.x;
    const float* src = w + (size_t)row * cols;
    __half* dst = o + (size_t)row * cols;
    float ss = 0.f;
    for (int i = tid * 4; i < cols; i += 1024) {
        float4 v = *(const float4*)(src + i);
        ss += v.x*v.x + v.y*v.y + v.z*v.z + v.w*v.w;
    }
    #pragma unroll
    for (int off = 16; off; off >>= 1) ss += __shfl_xor_sync(0xffffffffu, ss, off);
    __shared__ float red[8];
    if ((tid & 31) == 0) red[tid >> 5] = ss;
    __syncthreads();
    float total = 0.f;
    #pragma unroll
    for (int i = 0; i < 8; i++) total += red[i];
    float r = rsqrtf(total + 1e-6f);
    for (int i = tid * 4; i < cols; i += 1024) {
        float4 v = *(const float4*)(src + i);
        unsigned* op = (unsigned*)(dst + i);
        op[0] = pack_h2(v.x * r, v.y * r);
        op[1] = pack_h2(v.z * r, v.w * r);
    }
}

// ---------------------------------------------------------------------------
// FP16 GEMM: BK=32, 3-stage cp.async pipeline + ldmatrix (round-13 version).
// ---------------------------------------------------------------------------
#define HBKP 40
#define HSTG_B 20480
#define GEMM_SMEM (3 * HSTG_B)

__global__ void __launch_bounds__(256, 2) gemm_fp16(
    const __half* __restrict__ A, const __half* __restrict__ B,
    float* __restrict__ C, int M, int N, int K)
{
    __half* smem = (__half*)dyn_smem;

    int tid = threadIdx.x, lane = tid & 31, warp = tid >> 5;
    int wm = warp >> 2, wn = warp & 3;
    int mBase = blockIdx.y * 128, nBase = blockIdx.x * 128;
    int lr = lane >> 2, lc = lane & 3;
    int l7 = lane & 7, l8 = (lane >> 3) & 1, l16 = lane >> 4;

    int r0 = tid >> 2, o0 = (tid & 3) * 8;
    const __half* Ap0 = A + (size_t)(mBase + r0) * K + o0;
    const __half* Ap1 = A + (size_t)(mBase + r0 + 64) * K + o0;
    const __half* Bp0 = B + (size_t)(nBase + r0) * K + o0;
    const __half* Bp1 = B + (size_t)(nBase + r0 + 64) * K + o0;

    uint32_t sb = smem_to_u32(smem);
    uint32_t sA0 = sb + (r0 * HBKP + o0) * 2;
    uint32_t sA1 = sb + ((r0 + 64) * HBKP + o0) * 2;
    uint32_t sB0 = sA0 + 128 * HBKP * 2;
    uint32_t sB1 = sA1 + 128 * HBKP * 2;

    uint32_t aOff[4], bOff[2];
    #pragma unroll
    for (int mf = 0; mf < 4; mf++)
        aOff[mf] = ((wm * 64 + mf * 16 + l7 + l8 * 8) * HBKP + l16 * 8) * 2;
    #pragma unroll
    for (int nfp = 0; nfp < 2; nfp++)
        bOff[nfp] = ((wn * 32 + nfp * 16 + l16 * 8 + l7) * HBKP + l8 * 8) * 2;

    float acc[4][4][4];
    #pragma unroll
    for (int i = 0; i < 4; i++)
        #pragma unroll
        for (int j = 0; j < 4; j++)
            #pragma unroll
            for (int l = 0; l < 4; l++) acc[i][j][l] = 0.f;

    const int T = K / 32;

    #pragma unroll
    for (int s = 0; s < 2; s++) {
        uint32_t so = s * HSTG_B;
        int k0 = s * 32;
        cp_async16(sA0 + so, Ap0 + k0);
        cp_async16(sA1 + so, Ap1 + k0);
        cp_async16(sB0 + so, Bp0 + k0);
        cp_async16(sB1 + so, Bp1 + k0);
        CP_COMMIT();
    }

    for (int t = 0; t < T; t++) {
        CP_WAIT1();
        __syncthreads();

        if (t + 2 < T) {
            uint32_t so = ((t + 2) % 3) * HSTG_B;
            int k0 = (t + 2) * 32;
            cp_async16(sA0 + so, Ap0 + k0);
            cp_async16(sA1 + so, Ap1 + k0);
            cp_async16(sB0 + so, Bp0 + k0);
            cp_async16(sB1 + so, Bp1 + k0);
        }
        CP_COMMIT();

        uint32_t sS = sb + (t % 3) * HSTG_B;
        uint32_t sBB = sS + 128 * HBKP * 2;
        #pragma unroll
        for (int ch = 0; ch < 2; ch++) {
            uint32_t cB = ch * 32;
            unsigned a[4][4], b[4][2];
            #pragma unroll
            for (int mf = 0; mf < 4; mf++)
                ldsm_x4(a[mf][0], a[mf][1], a[mf][2], a[mf][3], sS + aOff[mf] + cB);
            #pragma unroll
            for (int nfp = 0; nfp < 2; nfp++) {
                unsigned q0, q1, q2, q3;
                ldsm_x4(q0, q1, q2, q3, sBB + bOff[nfp] + cB);
                b[2*nfp][0] = q0; b[2*nfp][1] = q1;
                b[2*nfp+1][0] = q2; b[2*nfp+1][1] = q3;
            }
            #pragma unroll
            for (int mf = 0; mf < 4; mf++)
                #pragma unroll
                for (int nf = 0; nf < 4; nf++)
                    mma_f16(acc[mf][nf], a[mf], b[nf]);
        }
    }

    #pragma unroll
    for (int mf = 0; mf < 4; mf++) {
        int row = mBase + wm * 64 + mf * 16 + lr;
        #pragma unroll
        for (int nf = 0; nf < 4; nf++) {
            int col = nBase + wn * 32 + nf * 8 + lc * 2;
            float2 v0 = {acc[mf][nf][0], acc[mf][nf][1]};
            float2 v1 = {acc[mf][nf][2], acc[mf][nf][3]};
            *(float2*)(C + (size_t)row * N + col)       = v0;
            *(float2*)(C + (size_t)(row + 8) * N + col) = v1;
        }
    }
}

// ---------------------------------------------------------------------------
// prep_qk: rms_norm q,k rows + split into (hi,lo) fp16 globals. 1 warp/row.
// ---------------------------------------------------------------------------
__global__ void __launch_bounds__(256) prep_qk(
    const float* __restrict__ qkv,
    __half* __restrict__ qh, __half* __restrict__ ql,
    __half* __restrict__ kh, __half* __restrict__ kl)
{
    int gw = (blockIdx.x * blockDim.x + threadIdx.x) >> 5;
    int lane = threadIdx.x & 31;
    int which = gw & 1;
    int t = gw >> 1;
    int h = t % HH;
    int bs = t / HH;
    const float* p = qkv + (size_t)bs * F3D + which * DD + h * HD + lane * 4;
    float4 v = *(const float4*)p;
    float ss = v.x*v.x + v.y*v.y + v.z*v.z + v.w*v.w;
    #pragma unroll
    for (int off = 16; off; off >>= 1) ss += __shfl_xor_sync(0xffffffffu, ss, off);
    float r = rsqrtf(ss * (1.f / HD) + 1e-6f);
    v.x *= r; v.y *= r; v.z *= r; v.w *= r;

    size_t oidx = (size_t)bs * DD + h * HD + lane * 4;
    __half* oh = (which ? kh : qh) + oidx;
    __half* ol = (which ? kl : ql) + oidx;
    unsigned hxy = pack_h2(v.x, v.y), hzw = pack_h2(v.z, v.w);
    __half2 hh0 = *(__half2*)&hxy, hh1 = *(__half2*)&hzw;
    float2 f0 = __half22float2(hh0), f1 = __half22float2(hh1);
    uint2 hi = {hxy, hzw};
    uint2 lo = {pack_h2(v.x - f0.x, v.y - f0.y), pack_h2(v.z - f1.x, v.w - f1.y)};
    *(uint2*)oh = hi;
    *(uint2*)ol = lo;
}

// ---------------------------------------------------------------------------
// vprep: pack V into transposed key-pair half2 layout [b,h,d,key2].
// ---------------------------------------------------------------------------
__global__ void __launch_bounds__(256) vprep(
    const float* __restrict__ qkv, unsigned* __restrict__ vt)
{
    int id = blockIdx.x * 256 + threadIdx.x;
    int lane = id & 31;
    int idx = id >> 5;
    int d4 = idx & 31;
    int k2b = (idx >> 5) & 31;
    int bh = idx >> 10;
    int b = bh >> 4, h = bh & 15;
    int key2 = k2b * 32 + lane;

    const float* p0 = qkv + ((size_t)(b * SS + 2 * key2)) * F3D + 2 * DD + h * HD + d4 * 4;
    float4 va = *(const float4*)p0;
    float4 vb = *(const float4*)(p0 + F3D);
    size_t base = ((size_t)bh * HD + d4 * 4) * (SS / 2) + key2;
    vt[base]                = pack_h2(va.x, vb.x);
    vt[base + (SS/2)]       = pack_h2(va.y, vb.y);
    vt[base + 2*(SS/2)]     = pack_h2(va.z, vb.z);
    vt[base + 3*(SS/2)]     = pack_h2(va.w, vb.w);
}

// ---------------------------------------------------------------------------
// FP16 flash attention v3: fixed-max softmax (unit-RMS bound), P in registers.
// smem (uints): Qh[128*68] Ql[128*68] | 2-stage KV ring.
// ---------------------------------------------------------------------------
#define QST 68
#define KST 68
#define VST2 36
#define KVU (64*KST*2 + 128*VST2)
#define ATT_SMEM ((128*QST*2 + 2*KVU) * 4)

__global__ void __launch_bounds__(256) flash_attn_fp16(
    const __half* __restrict__ qh, const __half* __restrict__ ql,
    const __half* __restrict__ kh, const __half* __restrict__ kl,
    const unsigned* __restrict__ vt, __half* __restrict__ out)
{
    uint32_t sbase = smem_to_u32(dyn_smem);
    uint32_t uQh = sbase;
    uint32_t uQl = sbase + 8704u * 4;
    uint32_t uKV0 = sbase + 17408u * 4;

    int tid = threadIdx.x, lane = tid & 31, wid = tid >> 5;
    int lr = lane >> 2, lc = lane & 3;
    int l7 = lane & 7, l8 = (lane >> 3) & 1, l16 = lane >> 4;
    int b = blockIdx.z, h = blockIdx.y;
    int qb = (int)gridDim.x - 1 - (int)blockIdx.x;
    int wrow = wid * 16;
    int bh = b * HH + h;

    uint32_t qOff = ((wrow + l7 + l8 * 8) * QST + l16 * 4) * 4;
    uint32_t kOff[4], vOff[8];
    #pragma unroll
    for (int nfp = 0; nfp < 4; nfp++)
        kOff[nfp] = ((nfp * 16 + l16 * 8 + l7) * KST + l8 * 4) * 4;
    #pragma unroll
    for (int nfp = 0; nfp < 8; nfp++)
        vOff[nfp] = (8704u + (nfp * 16 + l16 * 8 + l7) * VST2 + l8 * 4) * 4;

    const float scale = 0.08838834764831845f;      // 1/sqrt(128)
    // fixed softmax max = sqrt(128); fold 2^10 shift: arg offset = -sqrt(128)+ln(1024)
    const float eoff = -4.3822366f;

    {
        const __half* qhb = qh + ((size_t)(b * SS + qb * 128)) * DD + h * HD;
        const __half* qlb = ql + ((size_t)(b * SS + qb * 128)) * DD + h * HD;
        #pragma unroll
        for (int j = 0; j < 8; j++) {
            int lin = j * 256 + tid;
            int row = lin >> 4, ch = lin & 15;
            uint32_t d = (row * QST + ch * 4) * 4;
            cp_async16(uQh + d, qhb + (size_t)row * DD + ch * 8);
            cp_async16(uQl + d, qlb + (size_t)row * DD + ch * 8);
        }
    }

    int nIter = 2 * (qb + 1);
    const __half* khb = kh + (size_t)(b * SS) * DD + h * HD;
    const __half* klb = kl + (size_t)(b * SS) * DD + h * HD;
    const unsigned* vtb = vt + (size_t)bh * HD * (SS / 2);

    {
        #pragma unroll
        for (int j = 0; j < 4; j++) {
            int lin = j * 256 + tid;
            int row = lin >> 4, ch = lin & 15;
            uint32_t d = uKV0 + (row * KST + ch * 4) * 4;
            cp_async16(d, khb + (size_t)row * DD + ch * 8);
            cp_async16(d + 4352u * 4, klb + (size_t)row * DD + ch * 8);
        }
        #pragma unroll
        for (int j = 0; j < 4; j++) {
            int lin = j * 256 + tid;
            int dd = lin >> 3, ch = lin & 7;
            cp_async16(uKV0 + (8704u + dd * VST2 + ch * 4) * 4,
                       vtb + (size_t)dd * (SS / 2) + ch * 4);
        }
        CP_COMMIT();
    }

    float o[16][4];
    #pragma unroll
    for (int i = 0; i < 16; i++)
        #pragma unroll
        for (int j = 0; j < 4; j++) o[i][j] = 0.f;
    float l0 = 0.f, l1 = 0.f;

    int gr0 = qb * 128 + wrow + lr;
    int wmin = qb * 128 + wrow;

    for (int t = 0; t < nIter; t++) {
        int k0 = t * 64;
        uint32_t uS = uKV0 + (uint32_t)(t & 1) * (KVU * 4);

        if (t + 1 < nIter) {
            uint32_t uN = uKV0 + (uint32_t)((t + 1) & 1) * (KVU * 4);
            int kn = (t + 1) * 64;
            #pragma unroll
            for (int j = 0; j < 4; j++) {
                int lin = j * 256 + tid;
                int row = lin >> 4, ch = lin & 15;
                uint32_t d = uN + (row * KST + ch * 4) * 4;
                cp_async16(d, khb + (size_t)(kn + row) * DD + ch * 8);
                cp_async16(d + 4352u * 4, klb + (size_t)(kn + row) * DD + ch * 8);
            }
            #pragma unroll
            for (int j = 0; j < 4; j++) {
                int lin = j * 256 + tid;
                int dd = lin >> 3, ch = lin & 7;
                cp_async16(uN + (8704u + dd * VST2 + ch * 4) * 4,
                           vtb + (size_t)dd * (SS / 2) + kn / 2 + ch * 4);
            }
            CP_COMMIT();
            CP_WAIT1();
        } else {
            CP_WAIT0();
        }
        __syncthreads();

        // ---- S = Q K^T : 3-term fp16 ----
        float s[8][4];
        #pragma unroll
        for (int nf = 0; nf < 8; nf++)
            #pragma unroll
            for (int j = 0; j < 4; j++) s[nf][j] = 0.f;

        #pragma unroll
        for (int ks = 0; ks < 8; ks++) {
            unsigned ah[4], al[4];
            ldsm_x4(ah[0], ah[1], ah[2], ah[3], uQh + qOff + ks * 32);
            ldsm_x4(al[0], al[1], al[2], al[3], uQl + qOff + ks * 32);
            #pragma unroll
            for (int nfp = 0; nfp < 4; nfp++) {
                unsigned h0, h1, h2, h3, g0, g1, g2, g3;
                ldsm_x4(h0, h1, h2, h3, uS + kOff[nfp] + ks * 32);
                ldsm_x4(g0, g1, g2, g3, uS + 4352u * 4 + kOff[nfp] + ks * 32);
                unsigned bh0[2] = {h0, h1}, bh1[2] = {h2, h3};
                unsigned bl0[2] = {g0, g1}, bl1[2] = {g2, g3};
                mma_f16(s[2*nfp],   ah, bh0);
                mma_f16(s[2*nfp],   ah, bl0);
                mma_f16(s[2*nfp],   al, bh0);
                mma_f16(s[2*nfp+1], ah, bh1);
                mma_f16(s[2*nfp+1], ah, bl1);
                mma_f16(s[2*nfp+1], al, bh1);
            }
        }

        // ---- scale (+ causal mask only on diagonal-crossing tiles) ----
        if (k0 + 63 >= wmin) {
            #pragma unroll
            for (int nf = 0; nf < 8; nf++) {
                int c0 = k0 + nf * 8 + lc * 2;
                s[nf][0] = (c0     > gr0)     ? -INFINITY : s[nf][0] * scale;
                s[nf][1] = (c0 + 1 > gr0)     ? -INFINITY : s[nf][1] * scale;
                s[nf][2] = (c0     > gr0 + 8) ? -INFINITY : s[nf][2] * scale;
                s[nf][3] = (c0 + 1 > gr0 + 8) ? -INFINITY : s[nf][3] * scale;
            }
        } else {
            #pragma unroll
            for (int nf = 0; nf < 8; nf++) {
                s[nf][0] *= scale; s[nf][1] *= scale;
                s[nf][2] *= scale; s[nf][3] *= scale;
            }
        }

        // ---- fixed-max softmax: p = exp(s - sqrt(128)) * 1024 ----
        float ps0 = 0.f, ps1 = 0.f;
        unsigned pk[8][2];
        #pragma unroll
        for (int nf = 0; nf < 8; nf++) {
            float p0 = __expf(s[nf][0] + eoff);
            float p1 = __expf(s[nf][1] + eoff);
            float p2 = __expf(s[nf][2] + eoff);
            float p3 = __expf(s[nf][3] + eoff);
            ps0 += p0 + p1; ps1 += p2 + p3;
            pk[nf][0] = pack_h2(p0, p1);
            pk[nf][1] = pack_h2(p2, p3);
        }
        ps0 += __shfl_xor_sync(0xffffffffu, ps0, 1);
        ps0 += __shfl_xor_sync(0xffffffffu, ps0, 2);
        ps1 += __shfl_xor_sync(0xffffffffu, ps1, 1);
        ps1 += __shfl_xor_sync(0xffffffffu, ps1, 2);
        l0 += ps0;
        l1 += ps1;

        // ---- O += P V (P direct from registers: acc-frag == A-frag layout) ----
        #pragma unroll
        for (int ks = 0; ks < 4; ks++) {
            unsigned a4[4] = {pk[2*ks][0], pk[2*ks][1], pk[2*ks+1][0], pk[2*ks+1][1]};
            #pragma unroll
            for (int nfp = 0; nfp < 8; nfp++) {
                unsigned q0, q1, q2, q3;
                ldsm_x4(q0, q1, q2, q3, uS + vOff[nfp] + ks * 32);
                unsigned b0[2] = {q0, q1}, b1[2] = {q2, q3};
                mma_f16(o[2*nfp],   a4, b0);
                mma_f16(o[2*nfp+1], a4, b1);
            }
        }
        __syncthreads();
    }

    // ---- epilogue: /l, rms_norm, write half ----
    float il0 = 1.f / l0, il1 = 1.f / l1;
    float ss0 = 0.f, ss1 = 0.f;
    #pragma unroll
    for (int nf = 0; nf < 16; nf++) {
        o[nf][0] *= il0; o[nf][1] *= il0;
        o[nf][2] *= il1; o[nf][3] *= il1;
        ss0 += o[nf][0]*o[nf][0] + o[nf][1]*o[nf][1];
        ss1 += o[nf][2]*o[nf][2] + o[nf][3]*o[nf][3];
    }
    ss0 += __shfl_xor_sync(0xffffffffu, ss0, 1);
    ss0 += __shfl_xor_sync(0xffffffffu, ss0, 2);
    ss1 += __shfl_xor_sync(0xffffffffu, ss1, 1);
    ss1 += __shfl_xor_sync(0xffffffffu, ss1, 2);
    float rn0 = rsqrtf(ss0 * (1.f / HD) + 1e-6f);
    float rn1 = rsqrtf(ss1 * (1.f / HD) + 1e-6f);

    __half* o0 = out + ((size_t)(b * SS + gr0)) * DD + h * HD;
    __half* o1 = out + ((size_t)(b * SS + gr0 + 8)) * DD + h * HD;
    #pragma unroll
    for (int nf = 0; nf < 16; nf++) {
        int col = nf * 8 + lc * 2;
        *(unsigned*)(o0 + col) = pack_h2(o[nf][0] * rn0, o[nf][1] * rn0);
        *(unsigned*)(o1 + col) = pack_h2(o[nf][2] * rn1, o[nf][3] * rn1);
    }
}

// ---------------------------------------------------------------------------
extern "C" void kernel_launch(void* const* d_in, const int* in_sizes, int n_in,
                              void* d_out, int out_size)
{
    const float* x = nullptr; const float* w_in = nullptr; const float* w_out = nullptr;
    for (int i = 0; i < n_in; i++) {
        if (in_sizes[i] == BB * SS * DD)      x     = (const float*)d_in[i];
        else if (in_sizes[i] == F3D * DD)     w_in  = (const float*)d_in[i];
        else if (in_sizes[i] == DD * DD)      w_out = (const float*)d_in[i];
    }

    __half* xh;     cudaGetSymbolAddress((void**)&xh, g_xh);
    __half* win_h;  cudaGetSymbolAddress((void**)&win_h, g_win_h);
    __half* wout_h; cudaGetSymbolAddress((void**)&wout_h, g_wout_h);
    float*  qkv;    cudaGetSymbolAddress((void**)&qkv, g_qkv);
    __half* qh;     cudaGetSymbolAddress((void**)&qh, g_qh);
    __half* ql;     cudaGetSymbolAddress((void**)&ql, g_ql);
    __half* kh;     cudaGetSymbolAddress((void**)&kh, g_kh);
    __half* kl;     cudaGetSymbolAddress((void**)&kl, g_kl);
    unsigned* vt;   cudaGetSymbolAddress((void**)&vt, g_vt);
    __half* ah;     cudaGetSymbolAddress((void**)&ah, g_ah);

    cudaFuncSetAttribute(gemm_fp16, cudaFuncAttributeMaxDynamicSharedMemorySize, GEMM_SMEM);
    cudaFuncSetAttribute(flash_attn_fp16, cudaFuncAttributeMaxDynamicSharedMemorySize, ATT_SMEM);

    cvt_f2h<<<(MROWS * DD) / 1024, 256>>>(x, xh);
    unit_norm_rows_h<<<F3D, 256>>>(w_in, win_h, DD);
    unit_norm_rows_h<<<DD, 256>>>(w_out, wout_h, DD);

    {
        dim3 grid(F3D / 128, MROWS / 128);
        gemm_fp16<<<grid, 256, GEMM_SMEM>>>(xh, win_h, qkv, MROWS, F3D, DD);
    }
    {
        int blocks = (MROWS * 2 * HH) * 32 / 256;
        prep_qk<<<blocks, 256>>>(qkv, qh, ql, kh, kl);
        vprep<<<(BB * HH * 32 * 32 * 32) / 256, 256>>>(qkv, vt);
    }
    {
        dim3 grid(SS / 128, HH, BB);
        flash_attn_fp16<<<grid, 256, ATT_SMEM>>>(qh, ql, kh, kl, vt, ah);
    }
    {
        dim3 grid(DD / 128, MROWS / 128);
        gemm_fp16<<<grid, 256, GEMM_SMEM>>>(ah, wout_h, (float*)d_out, MROWS, DD, DD);
    }
}

// round 16
// speedup vs baseline: 1.1915x; 1.0326x over previous
#include <cuda_runtime.h>
#include <cuda_fp16.h>
#include <math.h>
#include <cstdint>

// Problem constants
#define BB 4
#define SS 2048
#define DD 2048
#define HH 16
#define HD 128
#define F3D (3*DD)          // 6144
#define MROWS (BB*SS)       // 8192

// Scratch (device globals; no allocation allowed)
__device__ __half g_xh[(size_t)MROWS * DD];
__device__ __half g_win_h[(size_t)F3D * DD];
__device__ __half g_wout_h[(size_t)DD * DD];
__device__ __half g_qh[(size_t)MROWS * DD];
__device__ __half g_ql[(size_t)MROWS * DD];
__device__ __half g_kh[(size_t)MROWS * DD];
__device__ __half g_kl[(size_t)MROWS * DD];
__device__ unsigned g_vt[(size_t)BB * HH * HD * (SS/2)];
__device__ __half g_ah[(size_t)MROWS * DD];

extern __shared__ __align__(16) char dyn_smem[];

// ---------------------------------------------------------------------------
__device__ __forceinline__ uint32_t smem_to_u32(const void* p) {
    uint32_t a;
    asm("{ .reg .u64 t; cvta.to.shared.u64 t, %1; cvt.u32.u64 %0, t; }" : "=r"(a) : "l"(p));
    return a;
}
__device__ __forceinline__ void cp_async16(uint32_t saddr, const void* gptr) {
    asm volatile("cp.async.cg.shared.global [%0], [%1], 16;" :: "r"(saddr), "l"(gptr));
}
#define CP_COMMIT() asm volatile("cp.async.commit_group;" ::: "memory")
#define CP_WAIT1()  asm volatile("cp.async.wait_group 1;" ::: "memory")
#define CP_WAIT0()  asm volatile("cp.async.wait_group 0;" ::: "memory")

__device__ __forceinline__ void mma_f16(float* c, const unsigned* a, const unsigned* b) {
    asm volatile(
        "mma.sync.aligned.m16n8k16.row.col.f32.f16.f16.f32 "
        "{%0,%1,%2,%3}, {%4,%5,%6,%7}, {%8,%9}, {%0,%1,%2,%3};"
        : "+f"(c[0]), "+f"(c[1]), "+f"(c[2]), "+f"(c[3])
        : "r"(a[0]), "r"(a[1]), "r"(a[2]), "r"(a[3]), "r"(b[0]), "r"(b[1]));
}
__device__ __forceinline__ void ldsm_x4(unsigned& r0, unsigned& r1, unsigned& r2,
                                        unsigned& r3, uint32_t addr) {
    asm volatile("ldmatrix.sync.aligned.m8n8.x4.shared.b16 {%0,%1,%2,%3}, [%4];"
        : "=r"(r0), "=r"(r1), "=r"(r2), "=r"(r3) : "r"(addr));
}
__device__ __forceinline__ unsigned pack_h2(float lo, float hi) {
    __half2 h = __floats2half2_rn(lo, hi);
    return *(unsigned*)&h;
}

// ---------------------------------------------------------------------------
__global__ void __launch_bounds__(256) cvt_f2h(const float* __restrict__ x,
                                               __half* __restrict__ xh)
{
    size_t i = ((size_t)blockIdx.x * 256 + threadIdx.x) * 4;
    float4 v = *(const float4*)(x + i);
    unsigned* o = (unsigned*)(xh + i);
    o[0] = pack_h2(v.x, v.y);
    o[1] = pack_h2(v.z, v.w);
}

// ---------------------------------------------------------------------------
__global__ void __launch_bounds__(256) unit_norm_rows_h(
    const float* __restrict__ w, __half* __restrict__ o, int cols)
{
    int row = blockIdx.x, tid = threadIdx.x;
    const float* src = w + (size_t)row * cols;
    __half* dst = o + (size_t)row * cols;
    float ss = 0.f;
    for (int i = tid * 4; i < cols; i += 1024) {
        float4 v = *(const float4*)(src + i);
        ss += v.x*v.x + v.y*v.y + v.z*v.z + v.w*v.w;
    }
    #pragma unroll
    for (int off = 16; off; off >>= 1) ss += __shfl_xor_sync(0xffffffffu, ss, off);
    __shared__ float red[8];
    if ((tid & 31) == 0) red[tid >> 5] = ss;
    __syncthreads();
    float total = 0.f;
    #pragma unroll
    for (int i = 0; i < 8; i++) total += red[i];
    float r = rsqrtf(total + 1e-6f);
    for (int i = tid * 4; i < cols; i += 1024) {
        float4 v = *(const float4*)(src + i);
        unsigned* op = (unsigned*)(dst + i);
        op[0] = pack_h2(v.x * r, v.y * r);
        op[1] = pack_h2(v.z * r, v.w * r);
    }
}

// ---------------------------------------------------------------------------
// Shared GEMM mainloop config
// ---------------------------------------------------------------------------
#define HBKP 40
#define HSTG_B 20480
#define GEMM_SMEM (3 * HSTG_B)

// Mainloop macro body (identical to round-13 gemm): computes acc[4][4][4].
#define GEMM_MAINLOOP(A, B, K)                                                  \
    __half* smem = (__half*)dyn_smem;                                           \
    int tid = threadIdx.x, lane = tid & 31, warp = tid >> 5;                    \
    int wm = warp >> 2, wn = warp & 3;                                          \
    int mBase = blockIdx.y * 128, nBase = blockIdx.x * 128;                     \
    int lr = lane >> 2, lc = lane & 3;                                          \
    int l7 = lane & 7, l8 = (lane >> 3) & 1, l16 = lane >> 4;                   \
    int r0 = tid >> 2, o0 = (tid & 3) * 8;                                      \
    const __half* Ap0 = A + (size_t)(mBase + r0) * K + o0;                      \
    const __half* Ap1 = A + (size_t)(mBase + r0 + 64) * K + o0;                 \
    const __half* Bp0 = B + (size_t)(nBase + r0) * K + o0;                      \
    const __half* Bp1 = B + (size_t)(nBase + r0 + 64) * K + o0;                 \
    uint32_t sb = smem_to_u32(smem);                                            \
    uint32_t sA0 = sb + (r0 * HBKP + o0) * 2;                                   \
    uint32_t sA1 = sb + ((r0 + 64) * HBKP + o0) * 2;                            \
    uint32_t sB0 = sA0 + 128 * HBKP * 2;                                        \
    uint32_t sB1 = sA1 + 128 * HBKP * 2;                                        \
    uint32_t aOff[4], bOff[2];                                                  \
    _Pragma("unroll")                                                           \
    for (int mf = 0; mf < 4; mf++)                                              \
        aOff[mf] = ((wm * 64 + mf * 16 + l7 + l8 * 8) * HBKP + l16 * 8) * 2;    \
    _Pragma("unroll")                                                           \
    for (int nfp = 0; nfp < 2; nfp++)                                           \
        bOff[nfp] = ((wn * 32 + nfp * 16 + l16 * 8 + l7) * HBKP + l8 * 8) * 2;  \
    float acc[4][4][4];                                                         \
    _Pragma("unroll")                                                           \
    for (int i = 0; i < 4; i++)                                                 \
        _Pragma("unroll")                                                       \
        for (int j = 0; j < 4; j++)                                             \
            _Pragma("unroll")                                                   \
            for (int l = 0; l < 4; l++) acc[i][j][l] = 0.f;                     \
    const int T = (K) / 32;                                                     \
    _Pragma("unroll")                                                           \
    for (int s = 0; s < 2; s++) {                                               \
        uint32_t so = s * HSTG_B;                                               \
        int k0 = s * 32;                                                        \
        cp_async16(sA0 + so, Ap0 + k0);                                         \
        cp_async16(sA1 + so, Ap1 + k0);                                         \
        cp_async16(sB0 + so, Bp0 + k0);                                         \
        cp_async16(sB1 + so, Bp1 + k0);                                         \
        CP_COMMIT();                                                            \
    }                                                                           \
    for (int t = 0; t < T; t++) {                                               \
        CP_WAIT1();                                                             \
        __syncthreads();                                                        \
        if (t + 2 < T) {                                                        \
            uint32_t so = ((t + 2) % 3) * HSTG_B;                               \
            int k0 = (t + 2) * 32;                                              \
            cp_async16(sA0 + so, Ap0 + k0);                                     \
            cp_async16(sA1 + so, Ap1 + k0);                                     \
            cp_async16(sB0 + so, Bp0 + k0);                                     \
            cp_async16(sB1 + so, Bp1 + k0);                                     \
        }                                                                       \
        CP_COMMIT();                                                            \
        uint32_t sS = sb + (t % 3) * HSTG_B;                                    \
        uint32_t sBB = sS + 128 * HBKP * 2;                                     \
        _Pragma("unroll")                                                       \
        for (int ch = 0; ch < 2; ch++) {                                        \
            uint32_t cB = ch * 32;                                              \
            unsigned a[4][4], b[4][2];                                          \
            _Pragma("unroll")                                                   \
            for (int mf = 0; mf < 4; mf++)                                      \
                ldsm_x4(a[mf][0], a[mf][1], a[mf][2], a[mf][3], sS + aOff[mf] + cB); \
            _Pragma("unroll")                                                   \
            for (int nfp = 0; nfp < 2; nfp++) {                                 \
                unsigned q0, q1, q2, q3;                                        \
                ldsm_x4(q0, q1, q2, q3, sBB + bOff[nfp] + cB);                  \
                b[2*nfp][0] = q0; b[2*nfp][1] = q1;                             \
                b[2*nfp+1][0] = q2; b[2*nfp+1][1] = q3;                         \
            }                                                                   \
            _Pragma("unroll")                                                   \
            for (int mf = 0; mf < 4; mf++)                                      \
                _Pragma("unroll")                                               \
                for (int nf = 0; nf < 4; nf++)                                  \
                    mma_f16(acc[mf][nf], a[mf], b[nf]);                         \
        }                                                                       \
    }

// ---------------------------------------------------------------------------
// GEMM2: plain fp32 output (round-13 epilogue).
// ---------------------------------------------------------------------------
__global__ void __launch_bounds__(256, 2) gemm_fp16(
    const __half* __restrict__ A, const __half* __restrict__ B,
    float* __restrict__ C, int M, int N, int K)
{
    GEMM_MAINLOOP(A, B, K)

    #pragma unroll
    for (int mf = 0; mf < 4; mf++) {
        int row = mBase + wm * 64 + mf * 16 + lr;
        #pragma unroll
        for (int nf = 0; nf < 4; nf++) {
            int col = nBase + wn * 32 + nf * 8 + lc * 2;
            float2 v0 = {acc[mf][nf][0], acc[mf][nf][1]};
            float2 v1 = {acc[mf][nf][2], acc[mf][nf][3]};
            *(float2*)(C + (size_t)row * N + col)       = v0;
            *(float2*)(C + (size_t)(row + 8) * N + col) = v1;
        }
    }
}

// ---------------------------------------------------------------------------
// GEMM1 fused: qkv projection with in-epilogue rms_norm+split (q,k) and
// transposed key-pair packing (v). N = 6144.
// ---------------------------------------------------------------------------
__global__ void __launch_bounds__(256, 2) gemm_qkv(
    const __half* __restrict__ A, const __half* __restrict__ B,
    __half* __restrict__ qh, __half* __restrict__ ql,
    __half* __restrict__ kh, __half* __restrict__ kl,
    unsigned* __restrict__ vt, int K)
{
    GEMM_MAINLOOP(A, B, K)

    __syncthreads();      // all warps done with stage smem -> reuse for reduce

    int region = nBase >> 11;                 // 0=q, 1=k, 2=v
    if (region < 2) {
        float* red = (float*)dyn_smem;        // [128 rows][4 wn]
        // per-thread partials over this warp's 32 cols (8 values per row)
        float pss[4][2];
        #pragma unroll
        for (int mf = 0; mf < 4; mf++) {
            float s0 = 0.f, s1 = 0.f;
            #pragma unroll
            for (int nf = 0; nf < 4; nf++) {
                s0 += acc[mf][nf][0]*acc[mf][nf][0] + acc[mf][nf][1]*acc[mf][nf][1];
                s1 += acc[mf][nf][2]*acc[mf][nf][2] + acc[mf][nf][3]*acc[mf][nf][3];
            }
            s0 += __shfl_xor_sync(0xffffffffu, s0, 1);
            s0 += __shfl_xor_sync(0xffffffffu, s0, 2);
            s1 += __shfl_xor_sync(0xffffffffu, s1, 1);
            s1 += __shfl_xor_sync(0xffffffffu, s1, 2);
            pss[mf][0] = s0; pss[mf][1] = s1;
        }
        if (lc == 0) {
            #pragma unroll
            for (int mf = 0; mf < 4; mf++) {
                int rr = wm * 64 + mf * 16 + lr;
                red[rr * 4 + wn]       = pss[mf][0];
                red[(rr + 8) * 4 + wn] = pss[mf][1];
            }
        }
        __syncthreads();

        __half* dh = region ? kh : qh;
        __half* dl = region ? kl : ql;
        int colbase = nBase - region * 2048;
        #pragma unroll
        for (int mf = 0; mf < 4; mf++) {
            int rr = wm * 64 + mf * 16 + lr;
            float ssa = red[rr*4] + red[rr*4+1] + red[rr*4+2] + red[rr*4+3];
            float ssb = red[(rr+8)*4] + red[(rr+8)*4+1] + red[(rr+8)*4+2] + red[(rr+8)*4+3];
            float rs0 = rsqrtf(ssa * (1.f / HD) + 1e-6f);
            float rs1 = rsqrtf(ssb * (1.f / HD) + 1e-6f);
            size_t row0 = (size_t)(mBase + rr) * DD;
            size_t row1 = (size_t)(mBase + rr + 8) * DD;
            #pragma unroll
            for (int nf = 0; nf < 4; nf++) {
                int col = colbase + wn * 32 + nf * 8 + lc * 2;
                float f0 = acc[mf][nf][0] * rs0, f1 = acc[mf][nf][1] * rs0;
                float f2 = acc[mf][nf][2] * rs1, f3 = acc[mf][nf][3] * rs1;
                unsigned u0 = pack_h2(f0, f1), u1 = pack_h2(f2, f3);
                __half2 h0 = *(__half2*)&u0, h1 = *(__half2*)&u1;
                float2 g0 = __half22float2(h0), g1 = __half22float2(h1);
                unsigned l0w = pack_h2(f0 - g0.x, f1 - g0.y);
                unsigned l1w = pack_h2(f2 - g1.x, f3 - g1.y);
                *(unsigned*)(dh + row0 + col) = u0;
                *(unsigned*)(dl + row0 + col) = l0w;
                *(unsigned*)(dh + row1 + col) = u1;
                *(unsigned*)(dl + row1 + col) = l1w;
            }
        }
    } else {
        // v region: pack row pairs (even,odd) into half2, transposed layout.
        int bglob = mBase >> 11;                   // batch (tile within one batch)
        int hloc = (nBase - 4096) >> 7;            // head
        unsigned bh_ = bglob * HH + hloc;
        #pragma unroll
        for (int mf = 0; mf < 4; mf++) {
            int rr = mBase + wm * 64 + mf * 16 + lr;
            int s0 = rr & (SS - 1);
            int key2a = s0 >> 1, key2b = (s0 + 8) >> 1;
            #pragma unroll
            for (int nf = 0; nf < 4; nf++) {
                int d = wn * 32 + nf * 8 + lc * 2;
                float p0 = __shfl_xor_sync(0xffffffffu, acc[mf][nf][0], 4);
                float p1 = __shfl_xor_sync(0xffffffffu, acc[mf][nf][1], 4);
                float p2 = __shfl_xor_sync(0xffffffffu, acc[mf][nf][2], 4);
                float p3 = __shfl_xor_sync(0xffffffffu, acc[mf][nf][3], 4);
                if (!(lr & 1)) {
                    size_t base = ((size_t)bh_ * HD + d) << 10;      // *(SS/2)
                    vt[base + key2a]          = pack_h2(acc[mf][nf][0], p0);
                    vt[base + (1 << 10) + key2a] = pack_h2(acc[mf][nf][1], p1);
                    vt[base + key2b]          = pack_h2(acc[mf][nf][2], p2);
                    vt[base + (1 << 10) + key2b] = pack_h2(acc[mf][nf][3], p3);
                }
            }
        }
    }
}

// ---------------------------------------------------------------------------
// FP16 flash attention (round-15 version, unchanged).
// ---------------------------------------------------------------------------
#define QST 68
#define KST 68
#define VST2 36
#define KVU (64*KST*2 + 128*VST2)
#define ATT_SMEM ((128*QST*2 + 2*KVU) * 4)

__global__ void __launch_bounds__(256) flash_attn_fp16(
    const __half* __restrict__ qh, const __half* __restrict__ ql,
    const __half* __restrict__ kh, const __half* __restrict__ kl,
    const unsigned* __restrict__ vt, __half* __restrict__ out)
{
    uint32_t sbase = smem_to_u32(dyn_smem);
    uint32_t uQh = sbase;
    uint32_t uQl = sbase + 8704u * 4;
    uint32_t uKV0 = sbase + 17408u * 4;

    int tid = threadIdx.x, lane = tid & 31, wid = tid >> 5;
    int lr = lane >> 2, lc = lane & 3;
    int l7 = lane & 7, l8 = (lane >> 3) & 1, l16 = lane >> 4;
    int b = blockIdx.z, h = blockIdx.y;
    int qb = (int)gridDim.x - 1 - (int)blockIdx.x;
    int wrow = wid * 16;
    int bh = b * HH + h;

    uint32_t qOff = ((wrow + l7 + l8 * 8) * QST + l16 * 4) * 4;
    uint32_t kOff[4], vOff[8];
    #pragma unroll
    for (int nfp = 0; nfp < 4; nfp++)
        kOff[nfp] = ((nfp * 16 + l16 * 8 + l7) * KST + l8 * 4) * 4;
    #pragma unroll
    for (int nfp = 0; nfp < 8; nfp++)
        vOff[nfp] = (8704u + (nfp * 16 + l16 * 8 + l7) * VST2 + l8 * 4) * 4;

    const float scale = 0.08838834764831845f;
    const float eoff = -4.3822366f;   // -sqrt(128) + ln(1024)

    {
        const __half* qhb = qh + ((size_t)(b * SS + qb * 128)) * DD + h * HD;
        const __half* qlb = ql + ((size_t)(b * SS + qb * 128)) * DD + h * HD;
        #pragma unroll
        for (int j = 0; j < 8; j++) {
            int lin = j * 256 + tid;
            int row = lin >> 4, ch = lin & 15;
            uint32_t d = (row * QST + ch * 4) * 4;
            cp_async16(uQh + d, qhb + (size_t)row * DD + ch * 8);
            cp_async16(uQl + d, qlb + (size_t)row * DD + ch * 8);
        }
    }

    int nIter = 2 * (qb + 1);
    const __half* khb = kh + (size_t)(b * SS) * DD + h * HD;
    const __half* klb = kl + (size_t)(b * SS) * DD + h * HD;
    const unsigned* vtb = vt + (size_t)bh * HD * (SS / 2);

    {
        #pragma unroll
        for (int j = 0; j < 4; j++) {
            int lin = j * 256 + tid;
            int row = lin >> 4, ch = lin & 15;
            uint32_t d = uKV0 + (row * KST + ch * 4) * 4;
            cp_async16(d, khb + (size_t)row * DD + ch * 8);
            cp_async16(d + 4352u * 4, klb + (size_t)row * DD + ch * 8);
        }
        #pragma unroll
        for (int j = 0; j < 4; j++) {
            int lin = j * 256 + tid;
            int dd = lin >> 3, ch = lin & 7;
            cp_async16(uKV0 + (8704u + dd * VST2 + ch * 4) * 4,
                       vtb + (size_t)dd * (SS / 2) + ch * 4);
        }
        CP_COMMIT();
    }

    float o[16][4];
    #pragma unroll
    for (int i = 0; i < 16; i++)
        #pragma unroll
        for (int j = 0; j < 4; j++) o[i][j] = 0.f;
    float l0 = 0.f, l1 = 0.f;

    int gr0 = qb * 128 + wrow + lr;
    int wmin = qb * 128 + wrow;

    for (int t = 0; t < nIter; t++) {
        int k0 = t * 64;
        uint32_t uS = uKV0 + (uint32_t)(t & 1) * (KVU * 4);

        if (t + 1 < nIter) {
            uint32_t uN = uKV0 + (uint32_t)((t + 1) & 1) * (KVU * 4);
            int kn = (t + 1) * 64;
            #pragma unroll
            for (int j = 0; j < 4; j++) {
                int lin = j * 256 + tid;
                int row = lin >> 4, ch = lin & 15;
                uint32_t d = uN + (row * KST + ch * 4) * 4;
                cp_async16(d, khb + (size_t)(kn + row) * DD + ch * 8);
                cp_async16(d + 4352u * 4, klb + (size_t)(kn + row) * DD + ch * 8);
            }
            #pragma unroll
            for (int j = 0; j < 4; j++) {
                int lin = j * 256 + tid;
                int dd = lin >> 3, ch = lin & 7;
                cp_async16(uN + (8704u + dd * VST2 + ch * 4) * 4,
                           vtb + (size_t)dd * (SS / 2) + kn / 2 + ch * 4);
            }
            CP_COMMIT();
            CP_WAIT1();
        } else {
            CP_WAIT0();
        }
        __syncthreads();

        float s[8][4];
        #pragma unroll
        for (int nf = 0; nf < 8; nf++)
            #pragma unroll
            for (int j = 0; j < 4; j++) s[nf][j] = 0.f;

        #pragma unroll
        for (int ks = 0; ks < 8; ks++) {
            unsigned ah[4], al[4];
            ldsm_x4(ah[0], ah[1], ah[2], ah[3], uQh + qOff + ks * 32);
            ldsm_x4(al[0], al[1], al[2], al[3], uQl + qOff + ks * 32);
            #pragma unroll
            for (int nfp = 0; nfp < 4; nfp++) {
                unsigned h0, h1, h2, h3, g0, g1, g2, g3;
                ldsm_x4(h0, h1, h2, h3, uS + kOff[nfp] + ks * 32);
                ldsm_x4(g0, g1, g2, g3, uS + 4352u * 4 + kOff[nfp] + ks * 32);
                unsigned bh0[2] = {h0, h1}, bh1[2] = {h2, h3};
                unsigned bl0[2] = {g0, g1}, bl1[2] = {g2, g3};
                mma_f16(s[2*nfp],   ah, bh0);
                mma_f16(s[2*nfp],   ah, bl0);
                mma_f16(s[2*nfp],   al, bh0);
                mma_f16(s[2*nfp+1], ah, bh1);
                mma_f16(s[2*nfp+1], ah, bl1);
                mma_f16(s[2*nfp+1], al, bh1);
            }
        }

        if (k0 + 63 >= wmin) {
            #pragma unroll
            for (int nf = 0; nf < 8; nf++) {
                int c0 = k0 + nf * 8 + lc * 2;
                s[nf][0] = (c0     > gr0)     ? -INFINITY : s[nf][0] * scale;
                s[nf][1] = (c0 + 1 > gr0)     ? -INFINITY : s[nf][1] * scale;
                s[nf][2] = (c0     > gr0 + 8) ? -INFINITY : s[nf][2] * scale;
                s[nf][3] = (c0 + 1 > gr0 + 8) ? -INFINITY : s[nf][3] * scale;
            }
        } else {
            #pragma unroll
            for (int nf = 0; nf < 8; nf++) {
                s[nf][0] *= scale; s[nf][1] *= scale;
                s[nf][2] *= scale; s[nf][3] *= scale;
            }
        }

        float ps0 = 0.f, ps1 = 0.f;
        unsigned pk[8][2];
        #pragma unroll
        for (int nf = 0; nf < 8; nf++) {
            float p0 = __expf(s[nf][0] + eoff);
            float p1 = __expf(s[nf][1] + eoff);
            float p2 = __expf(s[nf][2] + eoff);
            float p3 = __expf(s[nf][3] + eoff);
            ps0 += p0 + p1; ps1 += p2 + p3;
            pk[nf][0] = pack_h2(p0, p1);
            pk[nf][1] = pack_h2(p2, p3);
        }
        ps0 += __shfl_xor_sync(0xffffffffu, ps0, 1);
        ps0 += __shfl_xor_sync(0xffffffffu, ps0, 2);
        ps1 += __shfl_xor_sync(0xffffffffu, ps1, 1);
        ps1 += __shfl_xor_sync(0xffffffffu, ps1, 2);
        l0 += ps0;
        l1 += ps1;

        #pragma unroll
        for (int ks = 0; ks < 4; ks++) {
            unsigned a4[4] = {pk[2*ks][0], pk[2*ks][1], pk[2*ks+1][0], pk[2*ks+1][1]};
            #pragma unroll
            for (int nfp = 0; nfp < 8; nfp++) {
                unsigned q0, q1, q2, q3;
                ldsm_x4(q0, q1, q2, q3, uS + vOff[nfp] + ks * 32);
                unsigned b0[2] = {q0, q1}, b1[2] = {q2, q3};
                mma_f16(o[2*nfp],   a4, b0);
                mma_f16(o[2*nfp+1], a4, b1);
            }
        }
        __syncthreads();
    }

    float il0 = 1.f / l0, il1 = 1.f / l1;
    float ss0 = 0.f, ss1 = 0.f;
    #pragma unroll
    for (int nf = 0; nf < 16; nf++) {
        o[nf][0] *= il0; o[nf][1] *= il0;
        o[nf][2] *= il1; o[nf][3] *= il1;
        ss0 += o[nf][0]*o[nf][0] + o[nf][1]*o[nf][1];
        ss1 += o[nf][2]*o[nf][2] + o[nf][3]*o[nf][3];
    }
    ss0 += __shfl_xor_sync(0xffffffffu, ss0, 1);
    ss0 += __shfl_xor_sync(0xffffffffu, ss0, 2);
    ss1 += __shfl_xor_sync(0xffffffffu, ss1, 1);
    ss1 += __shfl_xor_sync(0xffffffffu, ss1, 2);
    float rn0 = rsqrtf(ss0 * (1.f / HD) + 1e-6f);
    float rn1 = rsqrtf(ss1 * (1.f / HD) + 1e-6f);

    __half* o0 = out + ((size_t)(b * SS + gr0)) * DD + h * HD;
    __half* o1 = out + ((size_t)(b * SS + gr0 + 8)) * DD + h * HD;
    #pragma unroll
    for (int nf = 0; nf < 16; nf++) {
        int col = nf * 8 + lc * 2;
        *(unsigned*)(o0 + col) = pack_h2(o[nf][0] * rn0, o[nf][1] * rn0);
        *(unsigned*)(o1 + col) = pack_h2(o[nf][2] * rn1, o[nf][3] * rn1);
    }
}

// ---------------------------------------------------------------------------
extern "C" void kernel_launch(void* const* d_in, const int* in_sizes, int n_in,
                              void* d_out, int out_size)
{
    const float* x = nullptr; const float* w_in = nullptr; const float* w_out = nullptr;
    for (int i = 0; i < n_in; i++) {
        if (in_sizes[i] == BB * SS * DD)      x     = (const float*)d_in[i];
        else if (in_sizes[i] == F3D * DD)     w_in  = (const float*)d_in[i];
        else if (in_sizes[i] == DD * DD)      w_out = (const float*)d_in[i];
    }

    __half* xh;     cudaGetSymbolAddress((void**)&xh, g_xh);
    __half* win_h;  cudaGetSymbolAddress((void**)&win_h, g_win_h);
    __half* wout_h; cudaGetSymbolAddress((void**)&wout_h, g_wout_h);
    __half* qh;     cudaGetSymbolAddress((void**)&qh, g_qh);
    __half* ql;     cudaGetSymbolAddress((void**)&ql, g_ql);
    __half* kh;     cudaGetSymbolAddress((void**)&kh, g_kh);
    __half* kl;     cudaGetSymbolAddress((void**)&kl, g_kl);
    unsigned* vt;   cudaGetSymbolAddress((void**)&vt, g_vt);
    __half* ah;     cudaGetSymbolAddress((void**)&ah, g_ah);

    cudaFuncSetAttribute(gemm_fp16, cudaFuncAttributeMaxDynamicSharedMemorySize, GEMM_SMEM);
    cudaFuncSetAttribute(gemm_qkv, cudaFuncAttributeMaxDynamicSharedMemorySize, GEMM_SMEM);
    cudaFuncSetAttribute(flash_attn_fp16, cudaFuncAttributeMaxDynamicSharedMemorySize, ATT_SMEM);

    cvt_f2h<<<(MROWS * DD) / 1024, 256>>>(x, xh);
    unit_norm_rows_h<<<F3D, 256>>>(w_in, win_h, DD);
    unit_norm_rows_h<<<DD, 256>>>(w_out, wout_h, DD);

    // fused qkv projection + rms/split + v transpose
    {
        dim3 grid(F3D / 128, MROWS / 128);
        gemm_qkv<<<grid, 256, GEMM_SMEM>>>(xh, win_h, qh, ql, kh, kl, vt, DD);
    }
    // attention
    {
        dim3 grid(SS / 128, HH, BB);
        flash_attn_fp16<<<grid, 256, ATT_SMEM>>>(qh, ql, kh, kl, vt, ah);
    }
    // out projection
    {
        dim3 grid(DD / 128, MROWS / 128);
        gemm_fp16<<<grid, 256, GEMM_SMEM>>>(ah, wout_h, (float*)d_out, MROWS, DD, DD);
    }
}

// round 17
// speedup vs baseline: 1.3092x; 1.0988x over previous
#include <cuda_runtime.h>
#include <cuda_fp16.h>
#include <math.h>
#include <cstdint>

// Problem constants
#define BB 4
#define SS 2048
#define DD 2048
#define HH 16
#define HD 128
#define F3D (3*DD)          // 6144
#define MROWS (BB*SS)       // 8192

// Scratch (device globals; no allocation allowed)
__device__ __half g_xh[(size_t)MROWS * DD];
__device__ __half g_win_h[(size_t)F3D * DD];
__device__ __half g_wout_h[(size_t)DD * DD];
__device__ __half g_qh[(size_t)MROWS * DD];
__device__ __half g_ql[(size_t)MROWS * DD];
__device__ __half g_kh[(size_t)MROWS * DD];
__device__ unsigned g_vt[(size_t)BB * HH * HD * (SS/2)];
__device__ __half g_ah[(size_t)MROWS * DD];

extern __shared__ __align__(16) char dyn_smem[];

// ---------------------------------------------------------------------------
__device__ __forceinline__ uint32_t smem_to_u32(const void* p) {
    uint32_t a;
    asm("{ .reg .u64 t; cvta.to.shared.u64 t, %1; cvt.u32.u64 %0, t; }" : "=r"(a) : "l"(p));
    return a;
}
__device__ __forceinline__ void cp_async16(uint32_t saddr, const void* gptr) {
    asm volatile("cp.async.cg.shared.global [%0], [%1], 16;" :: "r"(saddr), "l"(gptr));
}
#define CP_COMMIT() asm volatile("cp.async.commit_group;" ::: "memory")
#define CP_WAIT1()  asm volatile("cp.async.wait_group 1;" ::: "memory")
#define CP_WAIT0()  asm volatile("cp.async.wait_group 0;" ::: "memory")

__device__ __forceinline__ void mma_f16(float* c, const unsigned* a, const unsigned* b) {
    asm volatile(
        "mma.sync.aligned.m16n8k16.row.col.f32.f16.f16.f32 "
        "{%0,%1,%2,%3}, {%4,%5,%6,%7}, {%8,%9}, {%0,%1,%2,%3};"
        : "+f"(c[0]), "+f"(c[1]), "+f"(c[2]), "+f"(c[3])
        : "r"(a[0]), "r"(a[1]), "r"(a[2]), "r"(a[3]), "r"(b[0]), "r"(b[1]));
}
__device__ __forceinline__ void ldsm_x4(unsigned& r0, unsigned& r1, unsigned& r2,
                                        unsigned& r3, uint32_t addr) {
    asm volatile("ldmatrix.sync.aligned.m8n8.x4.shared.b16 {%0,%1,%2,%3}, [%4];"
        : "=r"(r0), "=r"(r1), "=r"(r2), "=r"(r3) : "r"(addr));
}
__device__ __forceinline__ unsigned pack_h2(float lo, float hi) {
    __half2 h = __floats2half2_rn(lo, hi);
    return *(unsigned*)&h;
}

// ---------------------------------------------------------------------------
__global__ void __launch_bounds__(256) cvt_f2h(const float* __restrict__ x,
                                               __half* __restrict__ xh)
{
    size_t i = ((size_t)blockIdx.x * 256 + threadIdx.x) * 4;
    float4 v = *(const float4*)(x + i);
    unsigned* o = (unsigned*)(xh + i);
    o[0] = pack_h2(v.x, v.y);
    o[1] = pack_h2(v.z, v.w);
}

// ---------------------------------------------------------------------------
__global__ void __launch_bounds__(256) unit_norm_rows_h(
    const float* __restrict__ w, __half* __restrict__ o, int cols)
{
    int row = blockIdx.x, tid = threadIdx.x;
    const float* src = w + (size_t)row * cols;
    __half* dst = o + (size_t)row * cols;
    float ss = 0.f;
    for (int i = tid * 4; i < cols; i += 1024) {
        float4 v = *(const float4*)(src + i);
        ss += v.x*v.x + v.y*v.y + v.z*v.z + v.w*v.w;
    }
    #pragma unroll
    for (int off = 16; off; off >>= 1) ss += __shfl_xor_sync(0xffffffffu, ss, off);
    __shared__ float red[8];
    if ((tid & 31) == 0) red[tid >> 5] = ss;
    __syncthreads();
    float total = 0.f;
    #pragma unroll
    for (int i = 0; i < 8; i++) total += red[i];
    float r = rsqrtf(total + 1e-6f);
    for (int i = tid * 4; i < cols; i += 1024) {
        float4 v = *(const float4*)(src + i);
        unsigned* op = (unsigned*)(dst + i);
        op[0] = pack_h2(v.x * r, v.y * r);
        op[1] = pack_h2(v.z * r, v.w * r);
    }
}

// ---------------------------------------------------------------------------
// Shared GEMM mainloop config
// ---------------------------------------------------------------------------
#define HBKP 40
#define HSTG_B 20480
#define GEMM_SMEM (3 * HSTG_B)

#define GEMM_MAINLOOP(A, B, K)                                                  \
    __half* smem = (__half*)dyn_smem;                                           \
    int tid = threadIdx.x, lane = tid & 31, warp = tid >> 5;                    \
    int wm = warp >> 2, wn = warp & 3;                                          \
    int mBase = blockIdx.y * 128, nBase = blockIdx.x * 128;                     \
    int lr = lane >> 2, lc = lane & 3;                                          \
    int l7 = lane & 7, l8 = (lane >> 3) & 1, l16 = lane >> 4;                   \
    int r0 = tid >> 2, o0 = (tid & 3) * 8;                                      \
    const __half* Ap0 = A + (size_t)(mBase + r0) * K + o0;                      \
    const __half* Ap1 = A + (size_t)(mBase + r0 + 64) * K + o0;                 \
    const __half* Bp0 = B + (size_t)(nBase + r0) * K + o0;                      \
    const __half* Bp1 = B + (size_t)(nBase + r0 + 64) * K + o0;                 \
    uint32_t sb = smem_to_u32(smem);                                            \
    uint32_t sA0 = sb + (r0 * HBKP + o0) * 2;                                   \
    uint32_t sA1 = sb + ((r0 + 64) * HBKP + o0) * 2;                            \
    uint32_t sB0 = sA0 + 128 * HBKP * 2;                                        \
    uint32_t sB1 = sA1 + 128 * HBKP * 2;                                        \
    uint32_t aOff[4], bOff[2];                                                  \
    _Pragma("unroll")                                                           \
    for (int mf = 0; mf < 4; mf++)                                              \
        aOff[mf] = ((wm * 64 + mf * 16 + l7 + l8 * 8) * HBKP + l16 * 8) * 2;    \
    _Pragma("unroll")                                                           \
    for (int nfp = 0; nfp < 2; nfp++)                                           \
        bOff[nfp] = ((wn * 32 + nfp * 16 + l16 * 8 + l7) * HBKP + l8 * 8) * 2;  \
    float acc[4][4][4];                                                         \
    _Pragma("unroll")                                                           \
    for (int i = 0; i < 4; i++)                                                 \
        _Pragma("unroll")                                                       \
        for (int j = 0; j < 4; j++)                                             \
            _Pragma("unroll")                                                   \
            for (int l = 0; l < 4; l++) acc[i][j][l] = 0.f;                     \
    const int T = (K) / 32;                                                     \
    _Pragma("unroll")                                                           \
    for (int s = 0; s < 2; s++) {                                               \
        uint32_t so = s * HSTG_B;                                               \
        int k0 = s * 32;                                                        \
        cp_async16(sA0 + so, Ap0 + k0);                                         \
        cp_async16(sA1 + so, Ap1 + k0);                                         \
        cp_async16(sB0 + so, Bp0 + k0);                                         \
        cp_async16(sB1 + so, Bp1 + k0);                                         \
        CP_COMMIT();                                                            \
    }                                                                           \
    for (int t = 0; t < T; t++) {                                               \
        CP_WAIT1();                                                             \
        __syncthreads();                                                        \
        if (t + 2 < T) {                                                        \
            uint32_t so = ((t + 2) % 3) * HSTG_B;                               \
            int k0 = (t + 2) * 32;                                              \
            cp_async16(sA0 + so, Ap0 + k0);                                     \
            cp_async16(sA1 + so, Ap1 + k0);                                     \
            cp_async16(sB0 + so, Bp0 + k0);                                     \
            cp_async16(sB1 + so, Bp1 + k0);                                     \
        }                                                                       \
        CP_COMMIT();                                                            \
        uint32_t sS = sb + (t % 3) * HSTG_B;                                    \
        uint32_t sBB = sS + 128 * HBKP * 2;                                     \
        _Pragma("unroll")                                                       \
        for (int ch = 0; ch < 2; ch++) {                                        \
            uint32_t cB = ch * 32;                                              \
            unsigned a[4][4], b[4][2];                                          \
            _Pragma("unroll")                                                   \
            for (int mf = 0; mf < 4; mf++)                                      \
                ldsm_x4(a[mf][0], a[mf][1], a[mf][2], a[mf][3], sS + aOff[mf] + cB); \
            _Pragma("unroll")                                                   \
            for (int nfp = 0; nfp < 2; nfp++) {                                 \
                unsigned q0, q1, q2, q3;                                        \
                ldsm_x4(q0, q1, q2, q3, sBB + bOff[nfp] + cB);                  \
                b[2*nfp][0] = q0; b[2*nfp][1] = q1;                             \
                b[2*nfp+1][0] = q2; b[2*nfp+1][1] = q3;                         \
            }                                                                   \
            _Pragma("unroll")                                                   \
            for (int mf = 0; mf < 4; mf++)                                      \
                _Pragma("unroll")                                               \
                for (int nf = 0; nf < 4; nf++)                                  \
                    mma_f16(acc[mf][nf], a[mf], b[nf]);                         \
        }                                                                       \
    }

// ---------------------------------------------------------------------------
// GEMM2: plain fp32 output.
// ---------------------------------------------------------------------------
__global__ void __launch_bounds__(256, 2) gemm_fp16(
    const __half* __restrict__ A, const __half* __restrict__ B,
    float* __restrict__ C, int M, int N, int K)
{
    GEMM_MAINLOOP(A, B, K)

    #pragma unroll
    for (int mf = 0; mf < 4; mf++) {
        int row = mBase + wm * 64 + mf * 16 + lr;
        #pragma unroll
        for (int nf = 0; nf < 4; nf++) {
            int col = nBase + wn * 32 + nf * 8 + lc * 2;
            float2 v0 = {acc[mf][nf][0], acc[mf][nf][1]};
            float2 v1 = {acc[mf][nf][2], acc[mf][nf][3]};
            *(float2*)(C + (size_t)row * N + col)       = v0;
            *(float2*)(C + (size_t)(row + 8) * N + col) = v1;
        }
    }
}

// ---------------------------------------------------------------------------
// GEMM1 fused: qkv projection; q -> (hi,lo) rms-normed, k -> hi rms-normed,
// v -> transposed key-pair pack.
// ---------------------------------------------------------------------------
__global__ void __launch_bounds__(256, 2) gemm_qkv(
    const __half* __restrict__ A, const __half* __restrict__ B,
    __half* __restrict__ qh, __half* __restrict__ ql,
    __half* __restrict__ kh, unsigned* __restrict__ vt, int K)
{
    GEMM_MAINLOOP(A, B, K)

    __syncthreads();

    int region = nBase >> 11;                 // 0=q, 1=k, 2=v
    if (region < 2) {
        float* red = (float*)dyn_smem;
        float pss[4][2];
        #pragma unroll
        for (int mf = 0; mf < 4; mf++) {
            float s0 = 0.f, s1 = 0.f;
            #pragma unroll
            for (int nf = 0; nf < 4; nf++) {
                s0 += acc[mf][nf][0]*acc[mf][nf][0] + acc[mf][nf][1]*acc[mf][nf][1];
                s1 += acc[mf][nf][2]*acc[mf][nf][2] + acc[mf][nf][3]*acc[mf][nf][3];
            }
            s0 += __shfl_xor_sync(0xffffffffu, s0, 1);
            s0 += __shfl_xor_sync(0xffffffffu, s0, 2);
            s1 += __shfl_xor_sync(0xffffffffu, s1, 1);
            s1 += __shfl_xor_sync(0xffffffffu, s1, 2);
            pss[mf][0] = s0; pss[mf][1] = s1;
        }
        if (lc == 0) {
            #pragma unroll
            for (int mf = 0; mf < 4; mf++) {
                int rr = wm * 64 + mf * 16 + lr;
                red[rr * 4 + wn]       = pss[mf][0];
                red[(rr + 8) * 4 + wn] = pss[mf][1];
            }
        }
        __syncthreads();

        __half* dh = region ? kh : qh;
        int colbase = nBase - region * 2048;
        #pragma unroll
        for (int mf = 0; mf < 4; mf++) {
            int rr = wm * 64 + mf * 16 + lr;
            float ssa = red[rr*4] + red[rr*4+1] + red[rr*4+2] + red[rr*4+3];
            float ssb = red[(rr+8)*4] + red[(rr+8)*4+1] + red[(rr+8)*4+2] + red[(rr+8)*4+3];
            float rs0 = rsqrtf(ssa * (1.f / HD) + 1e-6f);
            float rs1 = rsqrtf(ssb * (1.f / HD) + 1e-6f);
            size_t row0 = (size_t)(mBase + rr) * DD;
            size_t row1 = (size_t)(mBase + rr + 8) * DD;
            #pragma unroll
            for (int nf = 0; nf < 4; nf++) {
                int col = colbase + wn * 32 + nf * 8 + lc * 2;
                float f0 = acc[mf][nf][0] * rs0, f1 = acc[mf][nf][1] * rs0;
                float f2 = acc[mf][nf][2] * rs1, f3 = acc[mf][nf][3] * rs1;
                unsigned u0 = pack_h2(f0, f1), u1 = pack_h2(f2, f3);
                *(unsigned*)(dh + row0 + col) = u0;
                *(unsigned*)(dh + row1 + col) = u1;
                if (region == 0) {
                    __half2 h0 = *(__half2*)&u0, h1 = *(__half2*)&u1;
                    float2 g0 = __half22float2(h0), g1 = __half22float2(h1);
                    *(unsigned*)(ql + row0 + col) = pack_h2(f0 - g0.x, f1 - g0.y);
                    *(unsigned*)(ql + row1 + col) = pack_h2(f2 - g1.x, f3 - g1.y);
                }
            }
        }
    } else {
        int bglob = mBase >> 11;
        int hloc = (nBase - 4096) >> 7;
        unsigned bh_ = bglob * HH + hloc;
        #pragma unroll
        for (int mf = 0; mf < 4; mf++) {
            int rr = mBase + wm * 64 + mf * 16 + lr;
            int s0 = rr & (SS - 1);
            int key2a = s0 >> 1, key2b = (s0 + 8) >> 1;
            #pragma unroll
            for (int nf = 0; nf < 4; nf++) {
                int d = wn * 32 + nf * 8 + lc * 2;
                float p0 = __shfl_xor_sync(0xffffffffu, acc[mf][nf][0], 4);
                float p1 = __shfl_xor_sync(0xffffffffu, acc[mf][nf][1], 4);
                float p2 = __shfl_xor_sync(0xffffffffu, acc[mf][nf][2], 4);
                float p3 = __shfl_xor_sync(0xffffffffu, acc[mf][nf][3], 4);
                if (!(lr & 1)) {
                    size_t base = ((size_t)bh_ * HD + d) << 10;
                    vt[base + key2a]             = pack_h2(acc[mf][nf][0], p0);
                    vt[base + (1 << 10) + key2a] = pack_h2(acc[mf][nf][1], p1);
                    vt[base + key2b]             = pack_h2(acc[mf][nf][2], p2);
                    vt[base + (1 << 10) + key2b] = pack_h2(acc[mf][nf][3], p3);
                }
            }
        }
    }
}

// ---------------------------------------------------------------------------
// FP16 flash attention v4: QK = (qh+ql)*kh (2 terms), single-sync pipeline,
// fixed-max softmax, P in registers.
// smem (uints): Qh[128*68] Ql[128*68] | stage: K[64*68] + V[128*36] = 8960 u.
// ---------------------------------------------------------------------------
#define QST 68
#define KST 68
#define VST2 36
#define KVU (64*KST + 128*VST2)
#define ATT_SMEM ((128*QST*2 + 2*KVU) * 4)

__global__ void __launch_bounds__(256) flash_attn_fp16(
    const __half* __restrict__ qh, const __half* __restrict__ ql,
    const __half* __restrict__ kh,
    const unsigned* __restrict__ vt, __half* __restrict__ out)
{
    uint32_t sbase = smem_to_u32(dyn_smem);
    uint32_t uQh = sbase;
    uint32_t uQl = sbase + 8704u * 4;
    uint32_t uKV0 = sbase + 17408u * 4;

    int tid = threadIdx.x, lane = tid & 31, wid = tid >> 5;
    int lr = lane >> 2, lc = lane & 3;
    int l7 = lane & 7, l8 = (lane >> 3) & 1, l16 = lane >> 4;
    int b = blockIdx.z, h = blockIdx.y;
    int qb = (int)gridDim.x - 1 - (int)blockIdx.x;
    int wrow = wid * 16;
    int bh = b * HH + h;

    uint32_t qOff = ((wrow + l7 + l8 * 8) * QST + l16 * 4) * 4;
    uint32_t kOff[4], vOff[8];
    #pragma unroll
    for (int nfp = 0; nfp < 4; nfp++)
        kOff[nfp] = ((nfp * 16 + l16 * 8 + l7) * KST + l8 * 4) * 4;
    #pragma unroll
    for (int nfp = 0; nfp < 8; nfp++)
        vOff[nfp] = (4352u + (nfp * 16 + l16 * 8 + l7) * VST2 + l8 * 4) * 4;

    const float scale = 0.08838834764831845f;
    const float eoff = -4.3822366f;   // -sqrt(128) + ln(1024)

    int nIter = 2 * (qb + 1);
    const __half* khb = kh + (size_t)(b * SS) * DD + h * HD;
    const unsigned* vtb = vt + (size_t)bh * HD * (SS / 2);

    // prologue: stage Q (hi/lo) and KV tile 0
    {
        const __half* qhb = qh + ((size_t)(b * SS + qb * 128)) * DD + h * HD;
        const __half* qlb = ql + ((size_t)(b * SS + qb * 128)) * DD + h * HD;
        #pragma unroll
        for (int j = 0; j < 8; j++) {
            int lin = j * 256 + tid;
            int row = lin >> 4, ch = lin & 15;
            uint32_t d = (row * QST + ch * 4) * 4;
            cp_async16(uQh + d, qhb + (size_t)row * DD + ch * 8);
            cp_async16(uQl + d, qlb + (size_t)row * DD + ch * 8);
        }
        #pragma unroll
        for (int j = 0; j < 4; j++) {
            int lin = j * 256 + tid;
            int row = lin >> 4, ch = lin & 15;
            cp_async16(uKV0 + (row * KST + ch * 4) * 4,
                       khb + (size_t)row * DD + ch * 8);
        }
        #pragma unroll
        for (int j = 0; j < 4; j++) {
            int lin = j * 256 + tid;
            int dd = lin >> 3, ch = lin & 7;
            cp_async16(uKV0 + (4352u + dd * VST2 + ch * 4) * 4,
                       vtb + (size_t)dd * (SS / 2) + ch * 4);
        }
        CP_COMMIT();
    }

    float o[16][4];
    #pragma unroll
    for (int i = 0; i < 16; i++)
        #pragma unroll
        for (int j = 0; j < 4; j++) o[i][j] = 0.f;
    float l0 = 0.f, l1 = 0.f;

    int gr0 = qb * 128 + wrow + lr;
    int wmin = qb * 128 + wrow;

    for (int t = 0; t < nIter; t++) {
        int k0 = t * 64;
        uint32_t uS = uKV0 + (uint32_t)(t & 1) * (KVU * 4);

        CP_WAIT0();          // tile t resident
        __syncthreads();     // all readers of the other stage (iter t-1) done

        if (t + 1 < nIter) {
            uint32_t uN = uKV0 + (uint32_t)((t + 1) & 1) * (KVU * 4);
            int kn = (t + 1) * 64;
            #pragma unroll
            for (int j = 0; j < 4; j++) {
                int lin = j * 256 + tid;
                int row = lin >> 4, ch = lin & 15;
                cp_async16(uN + (row * KST + ch * 4) * 4,
                           khb + (size_t)(kn + row) * DD + ch * 8);
            }
            #pragma unroll
            for (int j = 0; j < 4; j++) {
                int lin = j * 256 + tid;
                int dd = lin >> 3, ch = lin & 7;
                cp_async16(uN + (4352u + dd * VST2 + ch * 4) * 4,
                           vtb + (size_t)dd * (SS / 2) + kn / 2 + ch * 4);
            }
            CP_COMMIT();
        }

        // ---- S = (Qh + Ql) K^T ----
        float s[8][4];
        #pragma unroll
        for (int nf = 0; nf < 8; nf++)
            #pragma unroll
            for (int j = 0; j < 4; j++) s[nf][j] = 0.f;

        #pragma unroll
        for (int ks = 0; ks < 8; ks++) {
            unsigned ah[4], al[4];
            ldsm_x4(ah[0], ah[1], ah[2], ah[3], uQh + qOff + ks * 32);
            ldsm_x4(al[0], al[1], al[2], al[3], uQl + qOff + ks * 32);
            #pragma unroll
            for (int nfp = 0; nfp < 4; nfp++) {
                unsigned h0, h1, h2, h3;
                ldsm_x4(h0, h1, h2, h3, uS + kOff[nfp] + ks * 32);
                unsigned bh0[2] = {h0, h1}, bh1[2] = {h2, h3};
                mma_f16(s[2*nfp],   ah, bh0);
                mma_f16(s[2*nfp],   al, bh0);
                mma_f16(s[2*nfp+1], ah, bh1);
                mma_f16(s[2*nfp+1], al, bh1);
            }
        }

        // ---- scale (+ causal mask only on diagonal-crossing tiles) ----
        if (k0 + 63 >= wmin) {
            #pragma unroll
            for (int nf = 0; nf < 8; nf++) {
                int c0 = k0 + nf * 8 + lc * 2;
                s[nf][0] = (c0     > gr0)     ? -INFINITY : s[nf][0] * scale;
                s[nf][1] = (c0 + 1 > gr0)     ? -INFINITY : s[nf][1] * scale;
                s[nf][2] = (c0     > gr0 + 8) ? -INFINITY : s[nf][2] * scale;
                s[nf][3] = (c0 + 1 > gr0 + 8) ? -INFINITY : s[nf][3] * scale;
            }
        } else {
            #pragma unroll
            for (int nf = 0; nf < 8; nf++) {
                s[nf][0] *= scale; s[nf][1] *= scale;
                s[nf][2] *= scale; s[nf][3] *= scale;
            }
        }

        // ---- fixed-max softmax ----
        float ps0 = 0.f, ps1 = 0.f;
        unsigned pk[8][2];
        #pragma unroll
        for (int nf = 0; nf < 8; nf++) {
            float p0 = __expf(s[nf][0] + eoff);
            float p1 = __expf(s[nf][1] + eoff);
            float p2 = __expf(s[nf][2] + eoff);
            float p3 = __expf(s[nf][3] + eoff);
            ps0 += p0 + p1; ps1 += p2 + p3;
            pk[nf][0] = pack_h2(p0, p1);
            pk[nf][1] = pack_h2(p2, p3);
        }
        ps0 += __shfl_xor_sync(0xffffffffu, ps0, 1);
        ps0 += __shfl_xor_sync(0xffffffffu, ps0, 2);
        ps1 += __shfl_xor_sync(0xffffffffu, ps1, 1);
        ps1 += __shfl_xor_sync(0xffffffffu, ps1, 2);
        l0 += ps0;
        l1 += ps1;

        // ---- O += P V ----
        #pragma unroll
        for (int ks = 0; ks < 4; ks++) {
            unsigned a4[4] = {pk[2*ks][0], pk[2*ks][1], pk[2*ks+1][0], pk[2*ks+1][1]};
            #pragma unroll
            for (int nfp = 0; nfp < 8; nfp++) {
                unsigned q0, q1, q2, q3;
                ldsm_x4(q0, q1, q2, q3, uS + vOff[nfp] + ks * 32);
                unsigned b0[2] = {q0, q1}, b1[2] = {q2, q3};
                mma_f16(o[2*nfp],   a4, b0);
                mma_f16(o[2*nfp+1], a4, b1);
            }
        }
    }

    // ---- epilogue: /l, rms_norm, write half ----
    float il0 = 1.f / l0, il1 = 1.f / l1;
    float ss0 = 0.f, ss1 = 0.f;
    #pragma unroll
    for (int nf = 0; nf < 16; nf++) {
        o[nf][0] *= il0; o[nf][1] *= il0;
        o[nf][2] *= il1; o[nf][3] *= il1;
        ss0 += o[nf][0]*o[nf][0] + o[nf][1]*o[nf][1];
        ss1 += o[nf][2]*o[nf][2] + o[nf][3]*o[nf][3];
    }
    ss0 += __shfl_xor_sync(0xffffffffu, ss0, 1);
    ss0 += __shfl_xor_sync(0xffffffffu, ss0, 2);
    ss1 += __shfl_xor_sync(0xffffffffu, ss1, 1);
    ss1 += __shfl_xor_sync(0xffffffffu, ss1, 2);
    float rn0 = rsqrtf(ss0 * (1.f / HD) + 1e-6f);
    float rn1 = rsqrtf(ss1 * (1.f / HD) + 1e-6f);

    __half* o0 = out + ((size_t)(b * SS + gr0)) * DD + h * HD;
    __half* o1 = out + ((size_t)(b * SS + gr0 + 8)) * DD + h * HD;
    #pragma unroll
    for (int nf = 0; nf < 16; nf++) {
        int col = nf * 8 + lc * 2;
        *(unsigned*)(o0 + col) = pack_h2(o[nf][0] * rn0, o[nf][1] * rn0);
        *(unsigned*)(o1 + col) = pack_h2(o[nf][2] * rn1, o[nf][3] * rn1);
    }
}

// ---------------------------------------------------------------------------
extern "C" void kernel_launch(void* const* d_in, const int* in_sizes, int n_in,
                              void* d_out, int out_size)
{
    const float* x = nullptr; const float* w_in = nullptr; const float* w_out = nullptr;
    for (int i = 0; i < n_in; i++) {
        if (in_sizes[i] == BB * SS * DD)      x     = (const float*)d_in[i];
        else if (in_sizes[i] == F3D * DD)     w_in  = (const float*)d_in[i];
        else if (in_sizes[i] == DD * DD)      w_out = (const float*)d_in[i];
    }

    __half* xh;     cudaGetSymbolAddress((void**)&xh, g_xh);
    __half* win_h;  cudaGetSymbolAddress((void**)&win_h, g_win_h);
    __half* wout_h; cudaGetSymbolAddress((void**)&wout_h, g_wout_h);
    __half* qh;     cudaGetSymbolAddress((void**)&qh, g_qh);
    __half* ql;     cudaGetSymbolAddress((void**)&ql, g_ql);
    __half* kh;     cudaGetSymbolAddress((void**)&kh, g_kh);
    unsigned* vt;   cudaGetSymbolAddress((void**)&vt, g_vt);
    __half* ah;     cudaGetSymbolAddress((void**)&ah, g_ah);

    cudaFuncSetAttribute(gemm_fp16, cudaFuncAttributeMaxDynamicSharedMemorySize, GEMM_SMEM);
    cudaFuncSetAttribute(gemm_qkv, cudaFuncAttributeMaxDynamicSharedMemorySize, GEMM_SMEM);
    cudaFuncSetAttribute(flash_attn_fp16, cudaFuncAttributeMaxDynamicSharedMemorySize, ATT_SMEM);

    cvt_f2h<<<(MROWS * DD) / 1024, 256>>>(x, xh);
    unit_norm_rows_h<<<F3D, 256>>>(w_in, win_h, DD);
    unit_norm_rows_h<<<DD, 256>>>(w_out, wout_h, DD);

    // fused qkv projection + rms/split + v transpose
    {
        dim3 grid(F3D / 128, MROWS / 128);
        gemm_qkv<<<grid, 256, GEMM_SMEM>>>(xh, win_h, qh, ql, kh, vt, DD);
    }
    // attention
    {
        dim3 grid(SS / 128, HH, BB);
        flash_attn_fp16<<<grid, 256, ATT_SMEM>>>(qh, ql, kh, vt, ah);
    }
    // out projection
    {
        dim3 grid(DD / 128, MROWS / 128);
        gemm_fp16<<<grid, 256, GEMM_SMEM>>>(ah, wout_h, (float*)d_out, MROWS, DD, DD);
    }
}